// round 1
// baseline (speedup 1.0000x reference)
#include <cuda_runtime.h>
#include <math.h>

// Problem constants
#define BB 4
#define SS 2048
#define DD 1024
#define HH 16
#define HDIM 64
#define MROWS (BB * SS)     /* 8192 */
#define NHEAD (HH * HDIM)   /* 1024 */

// Scratch (device globals: allocation-free)
__device__ float g_q[MROWS * NHEAD];
__device__ float g_k[MROWS * NHEAD];
__device__ float g_v[MROWS * NHEAD];
__device__ float g_ctx[MROWS * NHEAD];

// ---------------------------------------------------------------------------
// SGEMM: C = (A @ W + bias) * scale
// A: Mdim x Kdim row-major, W: Kdim x Ndim row-major, bias: Ndim, C: Mdim x Ndim
// BM=BN=128, BK=8, TM=TN=8, 256 threads.
// ---------------------------------------------------------------------------
__global__ void __launch_bounds__(256)
sgemm_bias(const float* __restrict__ A, const float* __restrict__ W,
           const float* __restrict__ bias, float* __restrict__ C,
           int Mdim, int Ndim, int Kdim, float scale)
{
    constexpr int BM = 128, BN = 128, BK = 8, TM = 8, TN = 8;
    __shared__ float As[BK][BM];   // A tile transposed: As[k][m]
    __shared__ float Bs[BK][BN];

    const int tid  = threadIdx.x;
    const int trow = tid >> 4;          // 0..15
    const int tcol = tid & 15;          // 0..15
    const int aRow = tid >> 1;          // 0..127
    const int aCol = (tid & 1) << 2;    // 0 or 4
    const int bRow = tid >> 5;          // 0..7
    const int bCol = (tid & 31) << 2;   // 0..124

    const float* Ap = A + (size_t)blockIdx.y * BM * Kdim;
    const float* Wp = W + (size_t)blockIdx.x * BN;

    float acc[TM][TN];
    #pragma unroll
    for (int i = 0; i < TM; ++i)
        #pragma unroll
        for (int j = 0; j < TN; ++j) acc[i][j] = 0.f;

    for (int k0 = 0; k0 < Kdim; k0 += BK) {
        float4 a4 = *(const float4*)(Ap + (size_t)aRow * Kdim + k0 + aCol);
        As[aCol + 0][aRow] = a4.x;
        As[aCol + 1][aRow] = a4.y;
        As[aCol + 2][aRow] = a4.z;
        As[aCol + 3][aRow] = a4.w;
        *(float4*)&Bs[bRow][bCol] =
            *(const float4*)(Wp + (size_t)(k0 + bRow) * Ndim + bCol);
        __syncthreads();

        #pragma unroll
        for (int kk = 0; kk < BK; ++kk) {
            float ra[TM], rb[TN];
            *(float4*)&ra[0] = *(const float4*)&As[kk][trow * TM];
            *(float4*)&ra[4] = *(const float4*)&As[kk][trow * TM + 4];
            *(float4*)&rb[0] = *(const float4*)&Bs[kk][tcol * TN];
            *(float4*)&rb[4] = *(const float4*)&Bs[kk][tcol * TN + 4];
            #pragma unroll
            for (int i = 0; i < TM; ++i)
                #pragma unroll
                for (int j = 0; j < TN; ++j)
                    acc[i][j] = fmaf(ra[i], rb[j], acc[i][j]);
        }
        __syncthreads();
    }

    #pragma unroll
    for (int i = 0; i < TM; ++i) {
        const size_t row = (size_t)blockIdx.y * BM + trow * TM + i;
        #pragma unroll
        for (int j = 0; j < TN; j += 4) {
            const int col = blockIdx.x * BN + tcol * TN + j;
            float4 bv = *(const float4*)(bias + col);
            float4 o;
            o.x = (acc[i][j + 0] + bv.x) * scale;
            o.y = (acc[i][j + 1] + bv.y) * scale;
            o.z = (acc[i][j + 2] + bv.z) * scale;
            o.w = (acc[i][j + 3] + bv.w) * scale;
            *(float4*)(C + row * Ndim + col) = o;
        }
    }
}

// ---------------------------------------------------------------------------
// Flash attention, fp32. One block = one (b,h) and 64 query rows.
// 256 threads as 16x16 (ty,tx); each thread owns a 4x4 fragment.
// Q is pre-scaled by 1/sqrt(HD) in the projection.
// q/k/v layout: ((b*S + s)*H + h)*HD + d  (row stride between s = 1024)
// ---------------------------------------------------------------------------
#define Q_PAD 68   /* transposed Q: Qst[d][r], float4-aligned rows */
#define K_PAD 65   /* natural K: Ks[r][d], scalar access, 2-way conflicts */
#define V_PAD 68   /* natural V: Vs[r][d], float4 rows */
#define P_PAD 68   /* transposed P: Pst[j][r], float4 rows */
#define FLASH_SMEM ((64 * (Q_PAD + K_PAD + V_PAD + P_PAD)) * 4) /* 68864 B */

__global__ void __launch_bounds__(256)
flash_attn(const float* __restrict__ Q, const float* __restrict__ K,
           const float* __restrict__ V, float* __restrict__ O)
{
    extern __shared__ float sm[];
    float* Qst = sm;                       // [64][Q_PAD]  (Qst[d*Q_PAD + r])
    float* Ks  = Qst + 64 * Q_PAD;         // [64][K_PAD]  (Ks[r*K_PAD + d])
    float* Vs  = Ks  + 64 * K_PAD;         // [64][V_PAD]  (Vs[r*V_PAD + d])
    float* Pst = Vs  + 64 * V_PAD;         // [64][P_PAD]  (Pst[j*P_PAD + r])

    const int tid = threadIdx.x;
    const int ty  = tid >> 4;   // 0..15 -> query rows ty*4..ty*4+3
    const int tx  = tid & 15;   // 0..15 -> cols tx*4..tx*4+3
    const int bh  = blockIdx.y;
    const int b   = bh >> 4;    // H = 16
    const int h   = bh & 15;
    const int q0  = blockIdx.x * 64;

    const size_t hoff = (size_t)h * HDIM;
    const float* Qg = Q + ((size_t)b * SS + q0) * NHEAD + hoff;
    const float* Kg = K + (size_t)b * SS * NHEAD + hoff;
    const float* Vg = V + (size_t)b * SS * NHEAD + hoff;

    // Load Q tile transposed: Qst[d][r]
    for (int idx = tid; idx < 1024; idx += 256) {
        int r  = idx >> 4;
        int dg = (idx & 15) << 2;
        float4 t = *(const float4*)(Qg + (size_t)r * NHEAD + dg);
        Qst[(dg + 0) * Q_PAD + r] = t.x;
        Qst[(dg + 1) * Q_PAD + r] = t.y;
        Qst[(dg + 2) * Q_PAD + r] = t.z;
        Qst[(dg + 3) * Q_PAD + r] = t.w;
    }

    float m_i[4], l_i[4], o[4][4];
    #pragma unroll
    for (int i = 0; i < 4; ++i) {
        m_i[i] = -1e30f;
        l_i[i] = 0.f;
        #pragma unroll
        for (int c = 0; c < 4; ++c) o[i][c] = 0.f;
    }

    for (int t0 = 0; t0 < SS; t0 += 64) {
        __syncthreads();  // prev-iter consumers done (also publishes Q on iter 0)

        // Load K (natural, scalar store) and V (natural, float4)
        for (int idx = tid; idx < 1024; idx += 256) {
            int r  = idx >> 4;
            int dg = (idx & 15) << 2;
            float4 t = *(const float4*)(Kg + (size_t)(t0 + r) * NHEAD + dg);
            Ks[r * K_PAD + dg + 0] = t.x;
            Ks[r * K_PAD + dg + 1] = t.y;
            Ks[r * K_PAD + dg + 2] = t.z;
            Ks[r * K_PAD + dg + 3] = t.w;
            float4 u = *(const float4*)(Vg + (size_t)(t0 + r) * NHEAD + dg);
            *(float4*)(Vs + r * V_PAD + dg) = u;
        }
        __syncthreads();

        // S = Q @ K^T  (64x64 tile, 4x4 frag per thread)
        float s[4][4];
        #pragma unroll
        for (int i = 0; i < 4; ++i)
            #pragma unroll
            for (int c = 0; c < 4; ++c) s[i][c] = 0.f;

        #pragma unroll 16
        for (int d = 0; d < 64; ++d) {
            float4 ra = *(const float4*)(Qst + d * Q_PAD + ty * 4);
            float rb0 = Ks[(tx * 4 + 0) * K_PAD + d];
            float rb1 = Ks[(tx * 4 + 1) * K_PAD + d];
            float rb2 = Ks[(tx * 4 + 2) * K_PAD + d];
            float rb3 = Ks[(tx * 4 + 3) * K_PAD + d];
            s[0][0] = fmaf(ra.x, rb0, s[0][0]); s[0][1] = fmaf(ra.x, rb1, s[0][1]);
            s[0][2] = fmaf(ra.x, rb2, s[0][2]); s[0][3] = fmaf(ra.x, rb3, s[0][3]);
            s[1][0] = fmaf(ra.y, rb0, s[1][0]); s[1][1] = fmaf(ra.y, rb1, s[1][1]);
            s[1][2] = fmaf(ra.y, rb2, s[1][2]); s[1][3] = fmaf(ra.y, rb3, s[1][3]);
            s[2][0] = fmaf(ra.z, rb0, s[2][0]); s[2][1] = fmaf(ra.z, rb1, s[2][1]);
            s[2][2] = fmaf(ra.z, rb2, s[2][2]); s[2][3] = fmaf(ra.z, rb3, s[2][3]);
            s[3][0] = fmaf(ra.w, rb0, s[3][0]); s[3][1] = fmaf(ra.w, rb1, s[3][1]);
            s[3][2] = fmaf(ra.w, rb2, s[3][2]); s[3][3] = fmaf(ra.w, rb3, s[3][3]);
        }

        // Online softmax (row reductions across the 16 tx lanes, width-16 shfl)
        #pragma unroll
        for (int i = 0; i < 4; ++i) {
            float mt = fmaxf(fmaxf(s[i][0], s[i][1]), fmaxf(s[i][2], s[i][3]));
            #pragma unroll
            for (int off = 8; off; off >>= 1)
                mt = fmaxf(mt, __shfl_xor_sync(0xffffffffu, mt, off, 16));
            float mnew = fmaxf(m_i[i], mt);
            float corr = __expf(m_i[i] - mnew);
            m_i[i] = mnew;
            float p0 = __expf(s[i][0] - mnew);
            float p1 = __expf(s[i][1] - mnew);
            float p2 = __expf(s[i][2] - mnew);
            float p3 = __expf(s[i][3] - mnew);
            float ls = p0 + p1 + p2 + p3;
            #pragma unroll
            for (int off = 8; off; off >>= 1)
                ls += __shfl_xor_sync(0xffffffffu, ls, off, 16);
            l_i[i] = l_i[i] * corr + ls;
            o[i][0] *= corr; o[i][1] *= corr; o[i][2] *= corr; o[i][3] *= corr;
            s[i][0] = p0; s[i][1] = p1; s[i][2] = p2; s[i][3] = p3;
        }

        // Write P transposed: Pst[key][row]
        #pragma unroll
        for (int c = 0; c < 4; ++c) {
            float4 pv = make_float4(s[0][c], s[1][c], s[2][c], s[3][c]);
            *(float4*)(Pst + (tx * 4 + c) * P_PAD + ty * 4) = pv;
        }
        __syncthreads();

        // O += P @ V
        #pragma unroll 16
        for (int j = 0; j < 64; ++j) {
            float4 ra = *(const float4*)(Pst + j * P_PAD + ty * 4);
            float4 rb = *(const float4*)(Vs + j * V_PAD + tx * 4);
            o[0][0] = fmaf(ra.x, rb.x, o[0][0]); o[0][1] = fmaf(ra.x, rb.y, o[0][1]);
            o[0][2] = fmaf(ra.x, rb.z, o[0][2]); o[0][3] = fmaf(ra.x, rb.w, o[0][3]);
            o[1][0] = fmaf(ra.y, rb.x, o[1][0]); o[1][1] = fmaf(ra.y, rb.y, o[1][1]);
            o[1][2] = fmaf(ra.y, rb.z, o[1][2]); o[1][3] = fmaf(ra.y, rb.w, o[1][3]);
            o[2][0] = fmaf(ra.z, rb.x, o[2][0]); o[2][1] = fmaf(ra.z, rb.y, o[2][1]);
            o[2][2] = fmaf(ra.z, rb.z, o[2][2]); o[2][3] = fmaf(ra.z, rb.w, o[2][3]);
            o[3][0] = fmaf(ra.w, rb.x, o[3][0]); o[3][1] = fmaf(ra.w, rb.y, o[3][1]);
            o[3][2] = fmaf(ra.w, rb.z, o[3][2]); o[3][3] = fmaf(ra.w, rb.w, o[3][3]);
        }
    }

    // Epilogue: normalize and store ctx
    float* Og = O + ((size_t)b * SS + q0) * NHEAD + hoff;
    #pragma unroll
    for (int i = 0; i < 4; ++i) {
        float inv = 1.f / l_i[i];
        float4 r = make_float4(o[i][0] * inv, o[i][1] * inv,
                               o[i][2] * inv, o[i][3] * inv);
        *(float4*)(Og + (size_t)(ty * 4 + i) * NHEAD + tx * 4) = r;
    }
}

// ---------------------------------------------------------------------------
extern "C" void kernel_launch(void* const* d_in, const int* in_sizes, int n_in,
                              void* d_out, int out_size)
{
    (void)in_sizes; (void)n_in; (void)out_size;
    const float* x  = (const float*)d_in[0];
    const float* Wq = (const float*)d_in[1];
    const float* bq = (const float*)d_in[2];
    const float* Wk = (const float*)d_in[3];
    const float* bk = (const float*)d_in[4];
    const float* Wv = (const float*)d_in[5];
    const float* bv = (const float*)d_in[6];
    const float* Wo = (const float*)d_in[7];
    const float* bo = (const float*)d_in[8];
    float* out = (float*)d_out;

    float *qp, *kp, *vp, *cp;
    cudaGetSymbolAddress((void**)&qp, g_q);
    cudaGetSymbolAddress((void**)&kp, g_k);
    cudaGetSymbolAddress((void**)&vp, g_v);
    cudaGetSymbolAddress((void**)&cp, g_ctx);

    cudaFuncSetAttribute(flash_attn,
                         cudaFuncAttributeMaxDynamicSharedMemorySize, FLASH_SMEM);

    dim3 ggrid(NHEAD / 128, MROWS / 128);  // (8, 64)

    // QKV projections (1/sqrt(HD) folded into Q)
    sgemm_bias<<<ggrid, 256>>>(x, Wq, bq, qp, MROWS, NHEAD, DD, 0.125f);
    sgemm_bias<<<ggrid, 256>>>(x, Wk, bk, kp, MROWS, NHEAD, DD, 1.0f);
    sgemm_bias<<<ggrid, 256>>>(x, Wv, bv, vp, MROWS, NHEAD, DD, 1.0f);

    // Attention
    flash_attn<<<dim3(SS / 64, BB * HH), 256, FLASH_SMEM>>>(qp, kp, vp, cp);

    // Output projection
    sgemm_bias<<<ggrid, 256>>>(cp, Wo, bo, out, MROWS, DD, NHEAD, 1.0f);
}

// round 3
// speedup vs baseline: 1.4552x; 1.4552x over previous
#include <cuda_runtime.h>
#include <cstdint>
#include <math.h>

// ============================================================================
// Problem constants
// ============================================================================
#define BB 4
#define SS 2048
#define DD 1024
#define HH 16
#define HDIM 64
#define MROWS (BB * SS)     /* 8192 */
#define NHEAD (HH * HDIM)   /* 1024 */

// Scratch (device globals: allocation-free)
__device__ float g_q[MROWS * NHEAD];
__device__ float g_k[MROWS * NHEAD];
__device__ float g_v[MROWS * NHEAD];
__device__ float g_ctx[MROWS * NHEAD];

// ============================================================================
// Helpers
// ============================================================================
__device__ __forceinline__ uint32_t smem_u32(const void* p) {
    uint32_t a;
    asm("{ .reg .u64 t; cvta.to.shared.u64 t, %1; cvt.u32.u64 %0, t; }"
        : "=r"(a) : "l"(p));
    return a;
}

// fp32 -> tf32 with round-to-nearest (unbiased; raw truncation would bias)
__device__ __forceinline__ uint32_t f2tf32(float x) {
    uint32_t u;
    asm("cvt.rna.tf32.f32 %0, %1;" : "=r"(u) : "f"(x));
    return u;
}

// m16n8k8 tf32 MMA (base ISA, works on plain sm_103 target)
__device__ __forceinline__ void mma_tf32(float* c, const uint32_t* a, const uint32_t* b) {
    asm volatile(
        "mma.sync.aligned.m16n8k8.row.col.f32.tf32.tf32.f32 "
        "{%0,%1,%2,%3}, {%4,%5,%6,%7}, {%8,%9}, {%0,%1,%2,%3};"
        : "+f"(c[0]), "+f"(c[1]), "+f"(c[2]), "+f"(c[3])
        : "r"(a[0]), "r"(a[1]), "r"(a[2]), "r"(a[3]), "r"(b[0]), "r"(b[1]));
}

#define CP16(dst, src) \
    asm volatile("cp.async.cg.shared.global [%0], [%1], 16;" \
        :: "r"(dst), "l"(src) : "memory")
#define CP_COMMIT() asm volatile("cp.async.commit_group;" ::: "memory")
#define CP_WAIT2()  asm volatile("cp.async.wait_group 2;" ::: "memory")
#define CP_WAIT0()  asm volatile("cp.async.wait_group 0;" ::: "memory")

// ============================================================================
// TF32 tensor-core GEMM via mma.sync:
//   C[8192 x 1024] = (A[8192 x 1024] @ W[1024 x 1024] + bias) * scale
// CTA tile 128x128, BK=16, 8 warps (2 M x 4 N), warp tile 64x32.
// 4-stage cp.async pipeline. A/W consumed natural row-major (mma B is
// col-major = W's [k][n] layout, no transpose needed).
// ============================================================================
#define GBM 128
#define GBN 128
#define GBK 16
#define AS_STRIDE 20    /* floats per A smem row (pad 16->20: conflict-free) */
#define BS_STRIDE 132   /* floats per B smem row (pad 128->132) */
#define AS_FLOATS (GBM * AS_STRIDE)          /* 2560 */
#define BS_FLOATS (GBK * BS_STRIDE)          /* 2112 */
#define STAGE_FLOATS (AS_FLOATS + BS_FLOATS) /* 4672 */
#define NSTAGE 4
#define GSMEM (NSTAGE * STAGE_FLOATS * 4)    /* 74752 bytes */

__global__ void __launch_bounds__(256, 2)
gemm_tf32(const float* __restrict__ A, const float* __restrict__ W,
          const float* __restrict__ bias, float* __restrict__ C,
          float scale)
{
    extern __shared__ float sm[];
    const uint32_t smb = smem_u32(sm);

    const int tid  = threadIdx.x;
    const int lane = tid & 31;
    const int wid  = tid >> 5;
    const int wm   = wid & 1;          // warp M index (0..1)
    const int wn   = wid >> 1;         // warp N index (0..3)
    const int gid  = lane >> 2;        // groupID 0..7
    const int tig  = lane & 3;         // thread-in-group 0..3
    const int m0   = blockIdx.y * GBM;
    const int n0   = blockIdx.x * GBN;

    // cp.async chunk assignments (512 16B-chunks each for A and B, 2/thread)
    const int am1 = tid >> 1,          ak1 = (tid & 1) << 3;          // A: m row, k offset (8 floats -> 2 chunks)
    const int bk1 = tid >> 5,          bn1 = (tid & 31) << 2;         // B: k row, n offset
    const int bk2 = (tid + 256) >> 5,  bn2 = (tid & 31) << 2;

    float acc[4][4][4];
    #pragma unroll
    for (int i = 0; i < 4; ++i)
        #pragma unroll
        for (int j = 0; j < 4; ++j)
            #pragma unroll
            for (int r = 0; r < 4; ++r) acc[i][j][r] = 0.f;

    const float* Ag = A + (size_t)m0 * 1024;
    const float* Wg = W + n0;

    // Stage loader: A tile (128x16) + B tile (16x128) for k-tile kt
    auto load_stage = [&](int s, int kt) {
        const uint32_t as = smb + (uint32_t)(s * STAGE_FLOATS) * 4;
        const uint32_t bs = as + AS_FLOATS * 4;
        const float* asrc = Ag + (size_t)am1 * 1024 + kt * GBK + ak1;
        uint32_t adst = as + (uint32_t)(am1 * AS_STRIDE + ak1) * 4;
        CP16(adst,      asrc);
        CP16(adst + 16, asrc + 4);
        const float* bsrc1 = Wg + (size_t)(kt * GBK + bk1) * 1024 + bn1;
        const float* bsrc2 = Wg + (size_t)(kt * GBK + bk2) * 1024 + bn2;
        CP16(bs + (uint32_t)(bk1 * BS_STRIDE + bn1) * 4, bsrc1);
        CP16(bs + (uint32_t)(bk2 * BS_STRIDE + bn2) * 4, bsrc2);
    };

    #pragma unroll
    for (int s = 0; s < 3; ++s) { load_stage(s, s); CP_COMMIT(); }

    for (int kt = 0; kt < 64; ++kt) {
        CP_WAIT2();          // this thread's stage-kt copies done
        __syncthreads();     // all threads' copies done; prev compute done

        if (kt + 3 < 64) load_stage((kt + 3) & 3, kt + 3);
        CP_COMMIT();

        const float* asp = sm + (kt & 3) * STAGE_FLOATS;
        const float* bsp = asp + AS_FLOATS;

        #pragma unroll
        for (int k8 = 0; k8 < 2; ++k8) {
            uint32_t a[4][4], b[4][2];
            #pragma unroll
            for (int i = 0; i < 4; ++i) {
                const float* ap = asp + (wm * 64 + i * 16 + gid) * AS_STRIDE
                                      + k8 * 8 + tig;
                a[i][0] = f2tf32(ap[0]);
                a[i][1] = f2tf32(ap[8 * AS_STRIDE]);
                a[i][2] = f2tf32(ap[4]);
                a[i][3] = f2tf32(ap[8 * AS_STRIDE + 4]);
            }
            #pragma unroll
            for (int j = 0; j < 4; ++j) {
                const float* bp = bsp + (k8 * 8 + tig) * BS_STRIDE
                                      + wn * 32 + j * 8 + gid;
                b[j][0] = f2tf32(bp[0]);
                b[j][1] = f2tf32(bp[4 * BS_STRIDE]);
            }
            #pragma unroll
            for (int i = 0; i < 4; ++i)
                #pragma unroll
                for (int j = 0; j < 4; ++j)
                    mma_tf32(acc[i][j], a[i], b[j]);
        }
    }
    CP_WAIT0();

    // Epilogue: bias + scale, float2 stores
    #pragma unroll
    for (int i = 0; i < 4; ++i) {
        const int row = m0 + wm * 64 + i * 16 + gid;
        #pragma unroll
        for (int j = 0; j < 4; ++j) {
            const int col = n0 + wn * 32 + j * 8 + (tig << 1);
            const float b0 = bias[col], b1 = bias[col + 1];
            float2 v0, v1;
            v0.x = (acc[i][j][0] + b0) * scale;
            v0.y = (acc[i][j][1] + b1) * scale;
            v1.x = (acc[i][j][2] + b0) * scale;
            v1.y = (acc[i][j][3] + b1) * scale;
            *(float2*)(C + (size_t)row * 1024 + col)       = v0;
            *(float2*)(C + (size_t)(row + 8) * 1024 + col) = v1;
        }
    }
}

// ============================================================================
// Flash attention, fp32 SIMT (unchanged from the passing R1 kernel).
// ============================================================================
#define Q_PAD 68
#define K_PAD 65
#define V_PAD 68
#define P_PAD 68
#define FLASH_SMEM ((64 * (Q_PAD + K_PAD + V_PAD + P_PAD)) * 4)

__global__ void __launch_bounds__(256)
flash_attn(const float* __restrict__ Q, const float* __restrict__ K,
           const float* __restrict__ V, float* __restrict__ O)
{
    extern __shared__ float smf[];
    float* Qst = smf;
    float* Ks  = Qst + 64 * Q_PAD;
    float* Vs  = Ks  + 64 * K_PAD;
    float* Pst = Vs  + 64 * V_PAD;

    const int tid = threadIdx.x;
    const int ty  = tid >> 4;
    const int tx  = tid & 15;
    const int bh  = blockIdx.y;
    const int b   = bh >> 4;
    const int h   = bh & 15;
    const int q0  = blockIdx.x * 64;

    const size_t hoff = (size_t)h * HDIM;
    const float* Qg = Q + ((size_t)b * SS + q0) * NHEAD + hoff;
    const float* Kg = K + (size_t)b * SS * NHEAD + hoff;
    const float* Vg = V + (size_t)b * SS * NHEAD + hoff;

    for (int idx = tid; idx < 1024; idx += 256) {
        int r  = idx >> 4;
        int dg = (idx & 15) << 2;
        float4 t = *(const float4*)(Qg + (size_t)r * NHEAD + dg);
        Qst[(dg + 0) * Q_PAD + r] = t.x;
        Qst[(dg + 1) * Q_PAD + r] = t.y;
        Qst[(dg + 2) * Q_PAD + r] = t.z;
        Qst[(dg + 3) * Q_PAD + r] = t.w;
    }

    float m_i[4], l_i[4], o[4][4];
    #pragma unroll
    for (int i = 0; i < 4; ++i) {
        m_i[i] = -1e30f;
        l_i[i] = 0.f;
        #pragma unroll
        for (int c = 0; c < 4; ++c) o[i][c] = 0.f;
    }

    for (int t0 = 0; t0 < SS; t0 += 64) {
        __syncthreads();

        for (int idx = tid; idx < 1024; idx += 256) {
            int r  = idx >> 4;
            int dg = (idx & 15) << 2;
            float4 t = *(const float4*)(Kg + (size_t)(t0 + r) * NHEAD + dg);
            Ks[r * K_PAD + dg + 0] = t.x;
            Ks[r * K_PAD + dg + 1] = t.y;
            Ks[r * K_PAD + dg + 2] = t.z;
            Ks[r * K_PAD + dg + 3] = t.w;
            float4 u = *(const float4*)(Vg + (size_t)(t0 + r) * NHEAD + dg);
            *(float4*)(Vs + r * V_PAD + dg) = u;
        }
        __syncthreads();

        float s[4][4];
        #pragma unroll
        for (int i = 0; i < 4; ++i)
            #pragma unroll
            for (int c = 0; c < 4; ++c) s[i][c] = 0.f;

        #pragma unroll 16
        for (int d = 0; d < 64; ++d) {
            float4 ra = *(const float4*)(Qst + d * Q_PAD + ty * 4);
            float rb0 = Ks[(tx * 4 + 0) * K_PAD + d];
            float rb1 = Ks[(tx * 4 + 1) * K_PAD + d];
            float rb2 = Ks[(tx * 4 + 2) * K_PAD + d];
            float rb3 = Ks[(tx * 4 + 3) * K_PAD + d];
            s[0][0] = fmaf(ra.x, rb0, s[0][0]); s[0][1] = fmaf(ra.x, rb1, s[0][1]);
            s[0][2] = fmaf(ra.x, rb2, s[0][2]); s[0][3] = fmaf(ra.x, rb3, s[0][3]);
            s[1][0] = fmaf(ra.y, rb0, s[1][0]); s[1][1] = fmaf(ra.y, rb1, s[1][1]);
            s[1][2] = fmaf(ra.y, rb2, s[1][2]); s[1][3] = fmaf(ra.y, rb3, s[1][3]);
            s[2][0] = fmaf(ra.z, rb0, s[2][0]); s[2][1] = fmaf(ra.z, rb1, s[2][1]);
            s[2][2] = fmaf(ra.z, rb2, s[2][2]); s[2][3] = fmaf(ra.z, rb3, s[2][3]);
            s[3][0] = fmaf(ra.w, rb0, s[3][0]); s[3][1] = fmaf(ra.w, rb1, s[3][1]);
            s[3][2] = fmaf(ra.w, rb2, s[3][2]); s[3][3] = fmaf(ra.w, rb3, s[3][3]);
        }

        #pragma unroll
        for (int i = 0; i < 4; ++i) {
            float mt = fmaxf(fmaxf(s[i][0], s[i][1]), fmaxf(s[i][2], s[i][3]));
            #pragma unroll
            for (int off = 8; off; off >>= 1)
                mt = fmaxf(mt, __shfl_xor_sync(0xffffffffu, mt, off, 16));
            float mnew = fmaxf(m_i[i], mt);
            float corr = __expf(m_i[i] - mnew);
            m_i[i] = mnew;
            float p0 = __expf(s[i][0] - mnew);
            float p1 = __expf(s[i][1] - mnew);
            float p2 = __expf(s[i][2] - mnew);
            float p3 = __expf(s[i][3] - mnew);
            float ls = p0 + p1 + p2 + p3;
            #pragma unroll
            for (int off = 8; off; off >>= 1)
                ls += __shfl_xor_sync(0xffffffffu, ls, off, 16);
            l_i[i] = l_i[i] * corr + ls;
            o[i][0] *= corr; o[i][1] *= corr; o[i][2] *= corr; o[i][3] *= corr;
            s[i][0] = p0; s[i][1] = p1; s[i][2] = p2; s[i][3] = p3;
        }

        #pragma unroll
        for (int c = 0; c < 4; ++c) {
            float4 pv = make_float4(s[0][c], s[1][c], s[2][c], s[3][c]);
            *(float4*)(Pst + (tx * 4 + c) * P_PAD + ty * 4) = pv;
        }
        __syncthreads();

        #pragma unroll 16
        for (int j = 0; j < 64; ++j) {
            float4 ra = *(const float4*)(Pst + j * P_PAD + ty * 4);
            float4 rb = *(const float4*)(Vs + j * V_PAD + tx * 4);
            o[0][0] = fmaf(ra.x, rb.x, o[0][0]); o[0][1] = fmaf(ra.x, rb.y, o[0][1]);
            o[0][2] = fmaf(ra.x, rb.z, o[0][2]); o[0][3] = fmaf(ra.x, rb.w, o[0][3]);
            o[1][0] = fmaf(ra.y, rb.x, o[1][0]); o[1][1] = fmaf(ra.y, rb.y, o[1][1]);
            o[1][2] = fmaf(ra.y, rb.z, o[1][2]); o[1][3] = fmaf(ra.y, rb.w, o[1][3]);
            o[2][0] = fmaf(ra.z, rb.x, o[2][0]); o[2][1] = fmaf(ra.z, rb.y, o[2][1]);
            o[2][2] = fmaf(ra.z, rb.z, o[2][2]); o[2][3] = fmaf(ra.z, rb.w, o[2][3]);
            o[3][0] = fmaf(ra.w, rb.x, o[3][0]); o[3][1] = fmaf(ra.w, rb.y, o[3][1]);
            o[3][2] = fmaf(ra.w, rb.z, o[3][2]); o[3][3] = fmaf(ra.w, rb.w, o[3][3]);
        }
    }

    float* Og = O + ((size_t)b * SS + q0) * NHEAD + hoff;
    #pragma unroll
    for (int i = 0; i < 4; ++i) {
        float inv = 1.f / l_i[i];
        float4 r = make_float4(o[i][0] * inv, o[i][1] * inv,
                               o[i][2] * inv, o[i][3] * inv);
        *(float4*)(Og + (size_t)(ty * 4 + i) * NHEAD + tx * 4) = r;
    }
}

// ============================================================================
extern "C" void kernel_launch(void* const* d_in, const int* in_sizes, int n_in,
                              void* d_out, int out_size)
{
    (void)in_sizes; (void)n_in; (void)out_size;
    const float* x  = (const float*)d_in[0];
    const float* Wq = (const float*)d_in[1];
    const float* bq = (const float*)d_in[2];
    const float* Wk = (const float*)d_in[3];
    const float* bk = (const float*)d_in[4];
    const float* Wv = (const float*)d_in[5];
    const float* bv = (const float*)d_in[6];
    const float* Wo = (const float*)d_in[7];
    const float* bo = (const float*)d_in[8];
    float* out = (float*)d_out;

    float *qp, *kp, *vp, *cp;
    cudaGetSymbolAddress((void**)&qp, g_q);
    cudaGetSymbolAddress((void**)&kp, g_k);
    cudaGetSymbolAddress((void**)&vp, g_v);
    cudaGetSymbolAddress((void**)&cp, g_ctx);

    cudaFuncSetAttribute(gemm_tf32,
                         cudaFuncAttributeMaxDynamicSharedMemorySize, GSMEM);
    cudaFuncSetAttribute(flash_attn,
                         cudaFuncAttributeMaxDynamicSharedMemorySize, FLASH_SMEM);

    dim3 ggrid(NHEAD / GBN, MROWS / GBM);  // (8, 64)

    // QKV projections on tensor cores (1/sqrt(HD) folded into Q's scale)
    gemm_tf32<<<ggrid, 256, GSMEM>>>(x, Wq, bq, qp, 0.125f);
    gemm_tf32<<<ggrid, 256, GSMEM>>>(x, Wk, bk, kp, 1.0f);
    gemm_tf32<<<ggrid, 256, GSMEM>>>(x, Wv, bv, vp, 1.0f);

    // Attention (fp32 SIMT)
    flash_attn<<<dim3(SS / 64, BB * HH), 256, FLASH_SMEM>>>(qp, kp, vp, cp);

    // Output projection on tensor cores
    gemm_tf32<<<ggrid, 256, GSMEM>>>(cp, Wo, bo, out, 1.0f);
}

// round 4
// speedup vs baseline: 3.3984x; 2.3354x over previous
#include <cuda_runtime.h>
#include <cstdint>
#include <math.h>

// ============================================================================
// Problem constants
// ============================================================================
#define BB 4
#define SS 2048
#define DD 1024
#define HH 16
#define HDIM 64
#define MROWS (BB * SS)     /* 8192 */
#define NHEAD (HH * HDIM)   /* 1024 */

// Scratch (device globals: allocation-free)
__device__ float g_q[MROWS * NHEAD];
__device__ float g_k[MROWS * NHEAD];
__device__ float g_v[MROWS * NHEAD];
__device__ float g_ctx[MROWS * NHEAD];

// ============================================================================
// Helpers
// ============================================================================
__device__ __forceinline__ uint32_t smem_u32(const void* p) {
    uint32_t a;
    asm("{ .reg .u64 t; cvta.to.shared.u64 t, %1; cvt.u32.u64 %0, t; }"
        : "=r"(a) : "l"(p));
    return a;
}

// fp32 -> tf32 round-to-nearest, result kept in fp32 slot
__device__ __forceinline__ uint32_t f2tf32(float x) {
    uint32_t u;
    asm("cvt.rna.tf32.f32 %0, %1;" : "=r"(u) : "f"(x));
    return u;
}
__device__ __forceinline__ float rna_tf32f(float x) {
    uint32_t u = f2tf32(x);
    return __uint_as_float(u);
}

// pack two fp32 -> bf16x2 (lo = first arg, hi = second), round-to-nearest
__device__ __forceinline__ uint32_t pack_bf16x2(float lo, float hi) {
    uint32_t r;
    asm("cvt.rn.bf16x2.f32 %0, %1, %2;" : "=r"(r) : "f"(hi), "f"(lo));
    return r;
}

// m16n8k8 tf32 MMA
__device__ __forceinline__ void mma_tf32(float* c, const uint32_t* a, const uint32_t* b) {
    asm volatile(
        "mma.sync.aligned.m16n8k8.row.col.f32.tf32.tf32.f32 "
        "{%0,%1,%2,%3}, {%4,%5,%6,%7}, {%8,%9}, {%0,%1,%2,%3};"
        : "+f"(c[0]), "+f"(c[1]), "+f"(c[2]), "+f"(c[3])
        : "r"(a[0]), "r"(a[1]), "r"(a[2]), "r"(a[3]), "r"(b[0]), "r"(b[1]));
}

// m16n8k16 bf16 MMA
__device__ __forceinline__ void mma_bf16(float* c, const uint32_t* a, const uint32_t* b) {
    asm volatile(
        "mma.sync.aligned.m16n8k16.row.col.f32.bf16.bf16.f32 "
        "{%0,%1,%2,%3}, {%4,%5,%6,%7}, {%8,%9}, {%0,%1,%2,%3};"
        : "+f"(c[0]), "+f"(c[1]), "+f"(c[2]), "+f"(c[3])
        : "r"(a[0]), "r"(a[1]), "r"(a[2]), "r"(a[3]), "r"(b[0]), "r"(b[1]));
}

#define CP16(dst, src) \
    asm volatile("cp.async.cg.shared.global [%0], [%1], 16;" \
        :: "r"(dst), "l"(src) : "memory")
#define CP_COMMIT() asm volatile("cp.async.commit_group;" ::: "memory")
#define CP_WAIT2()  asm volatile("cp.async.wait_group 2;" ::: "memory")
#define CP_WAIT0()  asm volatile("cp.async.wait_group 0;" ::: "memory")

// ============================================================================
// TF32 tensor-core GEMM (unchanged from R3 except optional rna epilogue):
//   C[8192 x 1024] = rnd((A @ W + bias) * scale)
// ============================================================================
#define GBM 128
#define GBN 128
#define GBK 16
#define AS_STRIDE 20
#define BS_STRIDE 132
#define AS_FLOATS (GBM * AS_STRIDE)
#define BS_FLOATS (GBK * BS_STRIDE)
#define STAGE_FLOATS (AS_FLOATS + BS_FLOATS)
#define NSTAGE 4
#define GSMEM (NSTAGE * STAGE_FLOATS * 4)

__global__ void __launch_bounds__(256, 2)
gemm_tf32(const float* __restrict__ A, const float* __restrict__ W,
          const float* __restrict__ bias, float* __restrict__ C,
          float scale, int rnd)
{
    extern __shared__ float sm[];
    const uint32_t smb = smem_u32(sm);

    const int tid  = threadIdx.x;
    const int lane = tid & 31;
    const int wid  = tid >> 5;
    const int wm   = wid & 1;
    const int wn   = wid >> 1;
    const int gid  = lane >> 2;
    const int tig  = lane & 3;
    const int m0   = blockIdx.y * GBM;
    const int n0   = blockIdx.x * GBN;

    const int am1 = tid >> 1,          ak1 = (tid & 1) << 3;
    const int bk1 = tid >> 5,          bn1 = (tid & 31) << 2;
    const int bk2 = (tid + 256) >> 5,  bn2 = (tid & 31) << 2;

    float acc[4][4][4];
    #pragma unroll
    for (int i = 0; i < 4; ++i)
        #pragma unroll
        for (int j = 0; j < 4; ++j)
            #pragma unroll
            for (int r = 0; r < 4; ++r) acc[i][j][r] = 0.f;

    const float* Ag = A + (size_t)m0 * 1024;
    const float* Wg = W + n0;

    auto load_stage = [&](int s, int kt) {
        const uint32_t as = smb + (uint32_t)(s * STAGE_FLOATS) * 4;
        const uint32_t bs = as + AS_FLOATS * 4;
        const float* asrc = Ag + (size_t)am1 * 1024 + kt * GBK + ak1;
        uint32_t adst = as + (uint32_t)(am1 * AS_STRIDE + ak1) * 4;
        CP16(adst,      asrc);
        CP16(adst + 16, asrc + 4);
        const float* bsrc1 = Wg + (size_t)(kt * GBK + bk1) * 1024 + bn1;
        const float* bsrc2 = Wg + (size_t)(kt * GBK + bk2) * 1024 + bn2;
        CP16(bs + (uint32_t)(bk1 * BS_STRIDE + bn1) * 4, bsrc1);
        CP16(bs + (uint32_t)(bk2 * BS_STRIDE + bn2) * 4, bsrc2);
    };

    #pragma unroll
    for (int s = 0; s < 3; ++s) { load_stage(s, s); CP_COMMIT(); }

    for (int kt = 0; kt < 64; ++kt) {
        CP_WAIT2();
        __syncthreads();

        if (kt + 3 < 64) load_stage((kt + 3) & 3, kt + 3);
        CP_COMMIT();

        const float* asp = sm + (kt & 3) * STAGE_FLOATS;
        const float* bsp = asp + AS_FLOATS;

        #pragma unroll
        for (int k8 = 0; k8 < 2; ++k8) {
            uint32_t a[4][4], b[4][2];
            #pragma unroll
            for (int i = 0; i < 4; ++i) {
                const float* ap = asp + (wm * 64 + i * 16 + gid) * AS_STRIDE
                                      + k8 * 8 + tig;
                a[i][0] = f2tf32(ap[0]);
                a[i][1] = f2tf32(ap[8 * AS_STRIDE]);
                a[i][2] = f2tf32(ap[4]);
                a[i][3] = f2tf32(ap[8 * AS_STRIDE + 4]);
            }
            #pragma unroll
            for (int j = 0; j < 4; ++j) {
                const float* bp = bsp + (k8 * 8 + tig) * BS_STRIDE
                                      + wn * 32 + j * 8 + gid;
                b[j][0] = f2tf32(bp[0]);
                b[j][1] = f2tf32(bp[4 * BS_STRIDE]);
            }
            #pragma unroll
            for (int i = 0; i < 4; ++i)
                #pragma unroll
                for (int j = 0; j < 4; ++j)
                    mma_tf32(acc[i][j], a[i], b[j]);
        }
    }
    CP_WAIT0();

    #pragma unroll
    for (int i = 0; i < 4; ++i) {
        const int row = m0 + wm * 64 + i * 16 + gid;
        #pragma unroll
        for (int j = 0; j < 4; ++j) {
            const int col = n0 + wn * 32 + j * 8 + (tig << 1);
            const float b0 = bias[col], b1 = bias[col + 1];
            float2 v0, v1;
            v0.x = (acc[i][j][0] + b0) * scale;
            v0.y = (acc[i][j][1] + b1) * scale;
            v1.x = (acc[i][j][2] + b0) * scale;
            v1.y = (acc[i][j][3] + b1) * scale;
            if (rnd) {
                v0.x = rna_tf32f(v0.x); v0.y = rna_tf32f(v0.y);
                v1.x = rna_tf32f(v1.x); v1.y = rna_tf32f(v1.y);
            }
            *(float2*)(C + (size_t)row * 1024 + col)       = v0;
            *(float2*)(C + (size_t)(row + 8) * 1024 + col) = v1;
        }
    }
}

// ============================================================================
// Tensor-core flash attention.
// CTA: 128 q-rows of one (b,h); 8 warps x 16 q-rows; 64-key tiles.
// QK^T: tf32 mma (Q,K pre-rounded rna-tf32 by GEMM epilogue -> no cvt here).
// PV:   bf16 mma; P passes C-frag -> A-frag in registers (no smem);
//       V transposed to bf16-pair smem with conflict-free lane mapping.
// ============================================================================
#define FQ 128
#define QS_STR 68
#define KS_STR 68
#define VS_STR 68
#define VT_STR 36   /* uint32 words per Vt row: 32 j-pairs + pad */
#define FL_FLOATS (FQ * QS_STR + 64 * KS_STR + 64 * VS_STR + 64 * VT_STR)
#define FL_SMEM (FL_FLOATS * 4)   /* 78848 bytes */

__global__ void __launch_bounds__(256, 2)
flash_tc(const float* __restrict__ Q, const float* __restrict__ K,
         const float* __restrict__ V, float* __restrict__ O)
{
    extern __shared__ float sm[];
    float*    Qs = sm;
    float*    Ks = Qs + FQ * QS_STR;
    float*    Vs = Ks + 64 * KS_STR;
    uint32_t* Vt = (uint32_t*)(Vs + 64 * VS_STR);

    const int tid  = threadIdx.x;
    const int w    = tid >> 5;
    const int lane = tid & 31;
    const int gid  = lane >> 2;
    const int tig  = lane & 3;
    const int bh   = blockIdx.y;
    const int b    = bh >> 4;
    const int h    = bh & 15;
    const int q0   = blockIdx.x * FQ;

    const float* Qg = Q + ((size_t)b * SS + q0) * NHEAD + h * HDIM;
    const float* Kg = K + (size_t)b * SS * NHEAD + h * HDIM;
    const float* Vg = V + (size_t)b * SS * NHEAD + h * HDIM;

    // Load Q tile (128 x 64), natural row-major
    #pragma unroll
    for (int i = 0; i < 8; ++i) {
        int idx = tid + i * 256;
        int r = idx >> 4, dg = (idx & 15) << 2;
        *(float4*)(Qs + r * QS_STR + dg) = *(const float4*)(Qg + (size_t)r * NHEAD + dg);
    }

    float m_[2] = {-1e30f, -1e30f};
    float l_[2] = {0.f, 0.f};
    float o[8][4];
    #pragma unroll
    for (int nt = 0; nt < 8; ++nt)
        #pragma unroll
        for (int r = 0; r < 4; ++r) o[nt][r] = 0.f;

    const int qr = w * 16 + gid;                 // this thread's base q-row
    const float* qrow0 = Qs + qr * QS_STR;
    const int jp = 4 * w + tig;                  // V-transpose column pair

    for (int t0 = 0; t0 < SS; t0 += 64) {
        __syncthreads();
        // Load K and V tiles (64 x 64 each), natural
        #pragma unroll
        for (int i = 0; i < 4; ++i) {
            int idx = tid + i * 256;
            int r = idx >> 4, dg = (idx & 15) << 2;
            *(float4*)(Ks + r * KS_STR + dg) =
                *(const float4*)(Kg + (size_t)(t0 + r) * NHEAD + dg);
            *(float4*)(Vs + r * VS_STR + dg) =
                *(const float4*)(Vg + (size_t)(t0 + r) * NHEAD + dg);
        }
        __syncthreads();

        // Transpose V -> Vt bf16 pairs: Vt[d][jp] = {V[2jp][d], V[2jp+1][d]}
        #pragma unroll
        for (int itd = 0; itd < 8; ++itd) {
            int d = gid + 8 * itd;
            float lo = Vs[(2 * jp)     * VS_STR + d];
            float hi = Vs[(2 * jp + 1) * VS_STR + d];
            Vt[d * VT_STR + jp] = pack_bf16x2(lo, hi);
        }

        // S = Q K^T (tf32), warp tile 16 x 64
        float s[8][4];
        #pragma unroll
        for (int nt = 0; nt < 8; ++nt)
            #pragma unroll
            for (int r = 0; r < 4; ++r) s[nt][r] = 0.f;

        #pragma unroll
        for (int ks = 0; ks < 8; ++ks) {
            uint32_t a[4];
            const float* qp = qrow0 + ks * 8 + tig;
            a[0] = __float_as_uint(qp[0]);
            a[1] = __float_as_uint(qp[8 * QS_STR]);
            a[2] = __float_as_uint(qp[4]);
            a[3] = __float_as_uint(qp[8 * QS_STR + 4]);
            #pragma unroll
            for (int nt = 0; nt < 8; ++nt) {
                const float* kp = Ks + (nt * 8 + gid) * KS_STR + ks * 8 + tig;
                uint32_t bb[2];
                bb[0] = __float_as_uint(kp[0]);
                bb[1] = __float_as_uint(kp[4]);
                mma_tf32(s[nt], a, bb);
            }
        }

        // Online softmax per row-half (rows gid / gid+8 across 4 lanes)
        #pragma unroll
        for (int hh = 0; hh < 2; ++hh) {
            const int c0 = 2 * hh, c1 = c0 + 1;
            float mt = fmaxf(s[0][c0], s[0][c1]);
            #pragma unroll
            for (int nt = 1; nt < 8; ++nt)
                mt = fmaxf(mt, fmaxf(s[nt][c0], s[nt][c1]));
            mt = fmaxf(mt, __shfl_xor_sync(0xffffffffu, mt, 1));
            mt = fmaxf(mt, __shfl_xor_sync(0xffffffffu, mt, 2));
            float mnew = fmaxf(m_[hh], mt);
            float corr = __expf(m_[hh] - mnew);
            m_[hh] = mnew;
            float ls = 0.f;
            #pragma unroll
            for (int nt = 0; nt < 8; ++nt) {
                s[nt][c0] = __expf(s[nt][c0] - mnew);
                s[nt][c1] = __expf(s[nt][c1] - mnew);
                ls += s[nt][c0] + s[nt][c1];
            }
            ls += __shfl_xor_sync(0xffffffffu, ls, 1);
            ls += __shfl_xor_sync(0xffffffffu, ls, 2);
            l_[hh] = l_[hh] * corr + ls;
            #pragma unroll
            for (int nt = 0; nt < 8; ++nt) {
                o[nt][c0] *= corr;
                o[nt][c1] *= corr;
            }
        }

        // Pack P: C-frag of S -> A-frag (bf16) for m16n8k16, in registers
        uint32_t pa[4][4];
        #pragma unroll
        for (int kc = 0; kc < 4; ++kc) {
            pa[kc][0] = pack_bf16x2(s[2 * kc][0],     s[2 * kc][1]);
            pa[kc][1] = pack_bf16x2(s[2 * kc][2],     s[2 * kc][3]);
            pa[kc][2] = pack_bf16x2(s[2 * kc + 1][0], s[2 * kc + 1][1]);
            pa[kc][3] = pack_bf16x2(s[2 * kc + 1][2], s[2 * kc + 1][3]);
        }

        __syncthreads();   // all Vt writes visible before PV reads

        // O += P V (bf16 mma), warp tile 16 x 64, k = 64 in 4 chunks
        #pragma unroll
        for (int kc = 0; kc < 4; ++kc) {
            #pragma unroll
            for (int nt = 0; nt < 8; ++nt) {
                const uint32_t* vp = Vt + (nt * 8 + gid) * VT_STR + kc * 8 + tig;
                uint32_t bb[2];
                bb[0] = vp[0];
                bb[1] = vp[4];
                mma_bf16(o[nt], pa[kc], bb);
            }
        }
    }

    // Epilogue: normalize, store ctx
    const float inv0 = 1.f / l_[0];
    const float inv1 = 1.f / l_[1];
    float* Og = O + ((size_t)b * SS + q0 + qr) * NHEAD + h * HDIM;
    #pragma unroll
    for (int nt = 0; nt < 8; ++nt) {
        float2 v;
        v.x = o[nt][0] * inv0;
        v.y = o[nt][1] * inv0;
        *(float2*)(Og + nt * 8 + 2 * tig) = v;
        v.x = o[nt][2] * inv1;
        v.y = o[nt][3] * inv1;
        *(float2*)(Og + (size_t)8 * NHEAD + nt * 8 + 2 * tig) = v;
    }
}

// ============================================================================
extern "C" void kernel_launch(void* const* d_in, const int* in_sizes, int n_in,
                              void* d_out, int out_size)
{
    (void)in_sizes; (void)n_in; (void)out_size;
    const float* x  = (const float*)d_in[0];
    const float* Wq = (const float*)d_in[1];
    const float* bq = (const float*)d_in[2];
    const float* Wk = (const float*)d_in[3];
    const float* bk = (const float*)d_in[4];
    const float* Wv = (const float*)d_in[5];
    const float* bv = (const float*)d_in[6];
    const float* Wo = (const float*)d_in[7];
    const float* bo = (const float*)d_in[8];
    float* out = (float*)d_out;

    float *qp, *kp, *vp, *cp;
    cudaGetSymbolAddress((void**)&qp, g_q);
    cudaGetSymbolAddress((void**)&kp, g_k);
    cudaGetSymbolAddress((void**)&vp, g_v);
    cudaGetSymbolAddress((void**)&cp, g_ctx);

    cudaFuncSetAttribute(gemm_tf32,
                         cudaFuncAttributeMaxDynamicSharedMemorySize, GSMEM);
    cudaFuncSetAttribute(flash_tc,
                         cudaFuncAttributeMaxDynamicSharedMemorySize, FL_SMEM);

    dim3 ggrid(NHEAD / GBN, MROWS / GBM);  // (8, 64)

    // QKV projections (1/sqrt(HD) folded into Q); Q,K pre-rounded to tf32
    gemm_tf32<<<ggrid, 256, GSMEM>>>(x, Wq, bq, qp, 0.125f, 1);
    gemm_tf32<<<ggrid, 256, GSMEM>>>(x, Wk, bk, kp, 1.0f, 1);
    gemm_tf32<<<ggrid, 256, GSMEM>>>(x, Wv, bv, vp, 1.0f, 0);

    // Tensor-core flash attention
    flash_tc<<<dim3(SS / FQ, BB * HH), 256, FL_SMEM>>>(qp, kp, vp, cp);

    // Output projection
    gemm_tf32<<<ggrid, 256, GSMEM>>>(cp, Wo, bo, out, 1.0f, 0);
}

// round 6
// speedup vs baseline: 3.4985x; 1.0294x over previous
#include <cuda_runtime.h>
#include <cstdint>
#include <math.h>

// ============================================================================
// Problem constants
// ============================================================================
#define BB 4
#define SS 2048
#define DD 1024
#define HH 16
#define HDIM 64
#define MROWS (BB * SS)     /* 8192 */
#define NHEAD (HH * HDIM)   /* 1024 */

// Scratch (device globals: allocation-free)
__device__ float g_q[MROWS * NHEAD];
__device__ float g_k[MROWS * NHEAD];
__device__ float g_v[MROWS * NHEAD];
__device__ float g_ctx[MROWS * NHEAD];

// ============================================================================
// Helpers
// ============================================================================
__device__ __forceinline__ uint32_t smem_u32(const void* p) {
    uint32_t a;
    asm("{ .reg .u64 t; cvta.to.shared.u64 t, %1; cvt.u32.u64 %0, t; }"
        : "=r"(a) : "l"(p));
    return a;
}

__device__ __forceinline__ uint32_t f2tf32(float x) {
    uint32_t u;
    asm("cvt.rna.tf32.f32 %0, %1;" : "=r"(u) : "f"(x));
    return u;
}
__device__ __forceinline__ float rna_tf32f(float x) {
    uint32_t u = f2tf32(x);
    return __uint_as_float(u);
}

// pack two fp32 -> fp16x2 {lo, hi}, round-to-nearest
__device__ __forceinline__ uint32_t pack_f16x2(float lo, float hi) {
    uint32_t r;
    asm("cvt.rn.f16x2.f32 %0, %1, %2;" : "=r"(r) : "f"(hi), "f"(lo));
    return r;
}

// m16n8k8 tf32 MMA
__device__ __forceinline__ void mma_tf32(float* c, const uint32_t* a, const uint32_t* b) {
    asm volatile(
        "mma.sync.aligned.m16n8k8.row.col.f32.tf32.tf32.f32 "
        "{%0,%1,%2,%3}, {%4,%5,%6,%7}, {%8,%9}, {%0,%1,%2,%3};"
        : "+f"(c[0]), "+f"(c[1]), "+f"(c[2]), "+f"(c[3])
        : "r"(a[0]), "r"(a[1]), "r"(a[2]), "r"(a[3]), "r"(b[0]), "r"(b[1]));
}

// m16n8k16 fp16 MMA (fp32 accumulate)
__device__ __forceinline__ void mma_f16(float* c, const uint32_t* a, const uint32_t* b) {
    asm volatile(
        "mma.sync.aligned.m16n8k16.row.col.f32.f16.f16.f32 "
        "{%0,%1,%2,%3}, {%4,%5,%6,%7}, {%8,%9}, {%0,%1,%2,%3};"
        : "+f"(c[0]), "+f"(c[1]), "+f"(c[2]), "+f"(c[3])
        : "r"(a[0]), "r"(a[1]), "r"(a[2]), "r"(a[3]), "r"(b[0]), "r"(b[1]));
}

#define CP16(dst, src) \
    asm volatile("cp.async.cg.shared.global [%0], [%1], 16;" \
        :: "r"(dst), "l"(src) : "memory")
#define CP_COMMIT() asm volatile("cp.async.commit_group;" ::: "memory")
#define CP_WAIT2()  asm volatile("cp.async.wait_group 2;" ::: "memory")
#define CP_WAIT0()  asm volatile("cp.async.wait_group 0;" ::: "memory")

// ============================================================================
// TF32 tensor-core GEMM (unchanged, proven):
//   C[8192 x 1024] = rnd((A @ W + bias) * scale)
// ============================================================================
#define GBM 128
#define GBN 128
#define GBK 16
#define AS_STRIDE 20
#define BS_STRIDE 132
#define AS_FLOATS (GBM * AS_STRIDE)
#define BS_FLOATS (GBK * BS_STRIDE)
#define STAGE_FLOATS (AS_FLOATS + BS_FLOATS)
#define NSTAGE 4
#define GSMEM (NSTAGE * STAGE_FLOATS * 4)

__global__ void __launch_bounds__(256, 2)
gemm_tf32(const float* __restrict__ A, const float* __restrict__ W,
          const float* __restrict__ bias, float* __restrict__ C,
          float scale, int rnd)
{
    extern __shared__ float sm[];
    const uint32_t smb = smem_u32(sm);

    const int tid  = threadIdx.x;
    const int lane = tid & 31;
    const int wid  = tid >> 5;
    const int wm   = wid & 1;
    const int wn   = wid >> 1;
    const int gid  = lane >> 2;
    const int tig  = lane & 3;
    const int m0   = blockIdx.y * GBM;
    const int n0   = blockIdx.x * GBN;

    const int am1 = tid >> 1,          ak1 = (tid & 1) << 3;
    const int bk1 = tid >> 5,          bn1 = (tid & 31) << 2;
    const int bk2 = (tid + 256) >> 5,  bn2 = (tid & 31) << 2;

    float acc[4][4][4];
    #pragma unroll
    for (int i = 0; i < 4; ++i)
        #pragma unroll
        for (int j = 0; j < 4; ++j)
            #pragma unroll
            for (int r = 0; r < 4; ++r) acc[i][j][r] = 0.f;

    const float* Ag = A + (size_t)m0 * 1024;
    const float* Wg = W + n0;

    auto load_stage = [&](int s, int kt) {
        const uint32_t as = smb + (uint32_t)(s * STAGE_FLOATS) * 4;
        const uint32_t bs = as + AS_FLOATS * 4;
        const float* asrc = Ag + (size_t)am1 * 1024 + kt * GBK + ak1;
        uint32_t adst = as + (uint32_t)(am1 * AS_STRIDE + ak1) * 4;
        CP16(adst,      asrc);
        CP16(adst + 16, asrc + 4);
        const float* bsrc1 = Wg + (size_t)(kt * GBK + bk1) * 1024 + bn1;
        const float* bsrc2 = Wg + (size_t)(kt * GBK + bk2) * 1024 + bn2;
        CP16(bs + (uint32_t)(bk1 * BS_STRIDE + bn1) * 4, bsrc1);
        CP16(bs + (uint32_t)(bk2 * BS_STRIDE + bn2) * 4, bsrc2);
    };

    #pragma unroll
    for (int s = 0; s < 3; ++s) { load_stage(s, s); CP_COMMIT(); }

    for (int kt = 0; kt < 64; ++kt) {
        CP_WAIT2();
        __syncthreads();

        if (kt + 3 < 64) load_stage((kt + 3) & 3, kt + 3);
        CP_COMMIT();

        const float* asp = sm + (kt & 3) * STAGE_FLOATS;
        const float* bsp = asp + AS_FLOATS;

        #pragma unroll
        for (int k8 = 0; k8 < 2; ++k8) {
            uint32_t a[4][4], b[4][2];
            #pragma unroll
            for (int i = 0; i < 4; ++i) {
                const float* ap = asp + (wm * 64 + i * 16 + gid) * AS_STRIDE
                                      + k8 * 8 + tig;
                a[i][0] = f2tf32(ap[0]);
                a[i][1] = f2tf32(ap[8 * AS_STRIDE]);
                a[i][2] = f2tf32(ap[4]);
                a[i][3] = f2tf32(ap[8 * AS_STRIDE + 4]);
            }
            #pragma unroll
            for (int j = 0; j < 4; ++j) {
                const float* bp = bsp + (k8 * 8 + tig) * BS_STRIDE
                                      + wn * 32 + j * 8 + gid;
                b[j][0] = f2tf32(bp[0]);
                b[j][1] = f2tf32(bp[4 * BS_STRIDE]);
            }
            #pragma unroll
            for (int i = 0; i < 4; ++i)
                #pragma unroll
                for (int j = 0; j < 4; ++j)
                    mma_tf32(acc[i][j], a[i], b[j]);
        }
    }
    CP_WAIT0();

    #pragma unroll
    for (int i = 0; i < 4; ++i) {
        const int row = m0 + wm * 64 + i * 16 + gid;
        #pragma unroll
        for (int j = 0; j < 4; ++j) {
            const int col = n0 + wn * 32 + j * 8 + (tig << 1);
            const float b0 = bias[col], b1 = bias[col + 1];
            float2 v0, v1;
            v0.x = (acc[i][j][0] + b0) * scale;
            v0.y = (acc[i][j][1] + b1) * scale;
            v1.x = (acc[i][j][2] + b0) * scale;
            v1.y = (acc[i][j][3] + b1) * scale;
            if (rnd) {
                v0.x = rna_tf32f(v0.x); v0.y = rna_tf32f(v0.y);
                v1.x = rna_tf32f(v1.x); v1.y = rna_tf32f(v1.y);
            }
            *(float2*)(C + (size_t)row * 1024 + col)       = v0;
            *(float2*)(C + (size_t)(row + 8) * 1024 + col) = v1;
        }
    }
}

// ============================================================================
// Tensor-core flash attention with cp.async pipeline (loader FIXED: full
// 16KB tiles = 4 chunks/thread, same mapping as the proven R4 loader).
// CTA: 128 q-rows of one (b,h); 8 warps x 16 q-rows; 64-key tiles, 32 iters.
// QK^T: tf32 mma. PV: fp16 mma, P via register passthrough, V transposed
// to fp16 pairs in smem. K double-buffered; V single-buffer staging.
// ============================================================================
#define FQ 128
#define QS_STR 68
#define KS_STR 68
#define VS_STR 68
#define VT_STR 36
#define FL_FLOATS (FQ * QS_STR + 2 * 64 * KS_STR + 64 * VS_STR + 64 * VT_STR)
#define FL_SMEM (FL_FLOATS * 4)   /* 96256 bytes */

__global__ void __launch_bounds__(256, 2)
flash_tc(const float* __restrict__ Q, const float* __restrict__ K,
         const float* __restrict__ V, float* __restrict__ O)
{
    extern __shared__ float sm[];
    float*    Qs  = sm;                            // [128][68]
    float*    Ks0 = Qs + FQ * QS_STR;              // [2][64][68]
    float*    Vs  = Ks0 + 2 * 64 * KS_STR;         // [64][68]
    uint32_t* Vt  = (uint32_t*)(Vs + 64 * VS_STR); // [64][36]

    const uint32_t smb    = smem_u32(sm);
    const uint32_t ks_smb = smb + (uint32_t)(FQ * QS_STR) * 4;
    const uint32_t vs_smb = ks_smb + (uint32_t)(2 * 64 * KS_STR) * 4;

    const int tid  = threadIdx.x;
    const int w    = tid >> 5;
    const int lane = tid & 31;
    const int gid  = lane >> 2;
    const int tig  = lane & 3;
    const int bh   = blockIdx.y;
    const int b    = bh >> 4;
    const int h    = bh & 15;
    const int q0   = blockIdx.x * FQ;

    const float* Qg = Q + ((size_t)b * SS + q0) * NHEAD + h * HDIM;
    const float* Kg = K + (size_t)b * SS * NHEAD + h * HDIM;
    const float* Vg = V + (size_t)b * SS * NHEAD + h * HDIM;

    // Full-tile async loaders: 64x64 floats = 1024 16B-chunks = 4/thread.
    auto load_k = [&](uint32_t dstbase, const float* src) {
        #pragma unroll
        for (int i = 0; i < 4; ++i) {
            int idx = tid + i * 256;
            int r = idx >> 4, c = (idx & 15) << 2;
            CP16(dstbase + (uint32_t)(r * KS_STR + c) * 4,
                 src + (size_t)r * NHEAD + c);
        }
    };
    auto load_v = [&](const float* src) {
        #pragma unroll
        for (int i = 0; i < 4; ++i) {
            int idx = tid + i * 256;
            int r = idx >> 4, c = (idx & 15) << 2;
            CP16(vs_smb + (uint32_t)(r * VS_STR + c) * 4,
                 src + (size_t)r * NHEAD + c);
        }
    };

    // Prologue: start K(0) -> buf 0, V(0) -> staging
    load_k(ks_smb, Kg);
    load_v(Vg);
    CP_COMMIT();

    // Load Q tile (128 x 64) while the DMA flies
    #pragma unroll
    for (int i = 0; i < 8; ++i) {
        int idx = tid + i * 256;
        int r = idx >> 4, dg = (idx & 15) << 2;
        *(float4*)(Qs + r * QS_STR + dg) = *(const float4*)(Qg + (size_t)r * NHEAD + dg);
    }

    float m_[2] = {-1e30f, -1e30f};
    float l_[2] = {0.f, 0.f};
    float o[8][4];
    #pragma unroll
    for (int nt = 0; nt < 8; ++nt)
        #pragma unroll
        for (int r = 0; r < 4; ++r) o[nt][r] = 0.f;

    const int qr = w * 16 + gid;
    const float* qrow0 = Qs + qr * QS_STR;
    const int jp = 4 * w + tig;                  // V-transpose pair column

    for (int it = 0; it < 32; ++it) {
        const int t0 = it * 64;
        CP_WAIT0();          // K(it), V(it) chunks of this thread arrived
        __syncthreads();     // all threads' chunks visible; prev iter retired

        // Transpose V -> Vt fp16 pairs: Vt[d][jp] = {V[2jp][d], V[2jp+1][d]}
        #pragma unroll
        for (int itd = 0; itd < 8; ++itd) {
            int d = gid + 8 * itd;
            float lo = Vs[(2 * jp)     * VS_STR + d];
            float hi = Vs[(2 * jp + 1) * VS_STR + d];
            Vt[d * VT_STR + jp] = pack_f16x2(lo, hi);
        }
        __syncthreads();     // Vt visible; Vs free for next V

        // Issue next tile's loads (K -> alternate buffer, V -> staging)
        if (it + 1 < 32) {
            load_k(ks_smb + (uint32_t)(((it + 1) & 1) * 64 * KS_STR) * 4,
                   Kg + (size_t)(t0 + 64) * NHEAD);
            load_v(Vg + (size_t)(t0 + 64) * NHEAD);
        }
        CP_COMMIT();

        const float* Ksb = Ks0 + (it & 1) * 64 * KS_STR;

        // S = Q K^T (tf32), warp tile 16 x 64
        float s[8][4];
        #pragma unroll
        for (int nt = 0; nt < 8; ++nt)
            #pragma unroll
            for (int r = 0; r < 4; ++r) s[nt][r] = 0.f;

        #pragma unroll
        for (int ks = 0; ks < 8; ++ks) {
            uint32_t a[4];
            const float* qp = qrow0 + ks * 8 + tig;
            a[0] = __float_as_uint(qp[0]);
            a[1] = __float_as_uint(qp[8 * QS_STR]);
            a[2] = __float_as_uint(qp[4]);
            a[3] = __float_as_uint(qp[8 * QS_STR + 4]);
            #pragma unroll
            for (int nt = 0; nt < 8; ++nt) {
                const float* kp = Ksb + (nt * 8 + gid) * KS_STR + ks * 8 + tig;
                uint32_t bb[2];
                bb[0] = __float_as_uint(kp[0]);
                bb[1] = __float_as_uint(kp[4]);
                mma_tf32(s[nt], a, bb);
            }
        }

        // Online softmax per row-half
        #pragma unroll
        for (int hh = 0; hh < 2; ++hh) {
            const int c0 = 2 * hh, c1 = c0 + 1;
            float mt = fmaxf(s[0][c0], s[0][c1]);
            #pragma unroll
            for (int nt = 1; nt < 8; ++nt)
                mt = fmaxf(mt, fmaxf(s[nt][c0], s[nt][c1]));
            mt = fmaxf(mt, __shfl_xor_sync(0xffffffffu, mt, 1));
            mt = fmaxf(mt, __shfl_xor_sync(0xffffffffu, mt, 2));
            float mnew = fmaxf(m_[hh], mt);
            float corr = __expf(m_[hh] - mnew);
            m_[hh] = mnew;
            float ls = 0.f;
            #pragma unroll
            for (int nt = 0; nt < 8; ++nt) {
                s[nt][c0] = __expf(s[nt][c0] - mnew);
                s[nt][c1] = __expf(s[nt][c1] - mnew);
                ls += s[nt][c0] + s[nt][c1];
            }
            ls += __shfl_xor_sync(0xffffffffu, ls, 1);
            ls += __shfl_xor_sync(0xffffffffu, ls, 2);
            l_[hh] = l_[hh] * corr + ls;
            #pragma unroll
            for (int nt = 0; nt < 8; ++nt) {
                o[nt][c0] *= corr;
                o[nt][c1] *= corr;
            }
        }

        // Pack P: S C-frag -> fp16 A-frag (registers only)
        uint32_t pa[4][4];
        #pragma unroll
        for (int kc = 0; kc < 4; ++kc) {
            pa[kc][0] = pack_f16x2(s[2 * kc][0],     s[2 * kc][1]);
            pa[kc][1] = pack_f16x2(s[2 * kc][2],     s[2 * kc][3]);
            pa[kc][2] = pack_f16x2(s[2 * kc + 1][0], s[2 * kc + 1][1]);
            pa[kc][3] = pack_f16x2(s[2 * kc + 1][2], s[2 * kc + 1][3]);
        }

        // O += P V (fp16 mma), warp tile 16 x 64
        #pragma unroll
        for (int kc = 0; kc < 4; ++kc) {
            #pragma unroll
            for (int nt = 0; nt < 8; ++nt) {
                const uint32_t* vp = Vt + (nt * 8 + gid) * VT_STR + kc * 8 + tig;
                uint32_t bb[2];
                bb[0] = vp[0];
                bb[1] = vp[4];
                mma_f16(o[nt], pa[kc], bb);
            }
        }
    }

    // Epilogue: normalize, store ctx
    const float inv0 = 1.f / l_[0];
    const float inv1 = 1.f / l_[1];
    float* Og = O + ((size_t)b * SS + q0 + qr) * NHEAD + h * HDIM;
    #pragma unroll
    for (int nt = 0; nt < 8; ++nt) {
        float2 v;
        v.x = o[nt][0] * inv0;
        v.y = o[nt][1] * inv0;
        *(float2*)(Og + nt * 8 + 2 * tig) = v;
        v.x = o[nt][2] * inv1;
        v.y = o[nt][3] * inv1;
        *(float2*)(Og + (size_t)8 * NHEAD + nt * 8 + 2 * tig) = v;
    }
}

// ============================================================================
extern "C" void kernel_launch(void* const* d_in, const int* in_sizes, int n_in,
                              void* d_out, int out_size)
{
    (void)in_sizes; (void)n_in; (void)out_size;
    const float* x  = (const float*)d_in[0];
    const float* Wq = (const float*)d_in[1];
    const float* bq = (const float*)d_in[2];
    const float* Wk = (const float*)d_in[3];
    const float* bk = (const float*)d_in[4];
    const float* Wv = (const float*)d_in[5];
    const float* bv = (const float*)d_in[6];
    const float* Wo = (const float*)d_in[7];
    const float* bo = (const float*)d_in[8];
    float* out = (float*)d_out;

    float *qp, *kp, *vp, *cp;
    cudaGetSymbolAddress((void**)&qp, g_q);
    cudaGetSymbolAddress((void**)&kp, g_k);
    cudaGetSymbolAddress((void**)&vp, g_v);
    cudaGetSymbolAddress((void**)&cp, g_ctx);

    cudaFuncSetAttribute(gemm_tf32,
                         cudaFuncAttributeMaxDynamicSharedMemorySize, GSMEM);
    cudaFuncSetAttribute(flash_tc,
                         cudaFuncAttributeMaxDynamicSharedMemorySize, FL_SMEM);

    dim3 ggrid(NHEAD / GBN, MROWS / GBM);  // (8, 64)

    // QKV projections (1/sqrt(HD) folded into Q); Q,K pre-rounded to tf32
    gemm_tf32<<<ggrid, 256, GSMEM>>>(x, Wq, bq, qp, 0.125f, 1);
    gemm_tf32<<<ggrid, 256, GSMEM>>>(x, Wk, bk, kp, 1.0f, 1);
    gemm_tf32<<<ggrid, 256, GSMEM>>>(x, Wv, bv, vp, 1.0f, 0);

    // Tensor-core flash attention (pipelined)
    flash_tc<<<dim3(SS / FQ, BB * HH), 256, FL_SMEM>>>(qp, kp, vp, cp);

    // Output projection
    gemm_tf32<<<ggrid, 256, GSMEM>>>(cp, Wo, bo, out, 1.0f, 0);
}

// round 7
// speedup vs baseline: 5.8578x; 1.6744x over previous
#include <cuda_runtime.h>
#include <cuda_fp16.h>
#include <cstdint>
#include <math.h>

// ============================================================================
// Problem constants
// ============================================================================
#define BB 4
#define SS 2048
#define DD 1024
#define HH 16
#define HDIM 64
#define MROWS (BB * SS)     /* 8192 */
#define NHEAD (HH * HDIM)   /* 1024 */

// Scratch (device globals: allocation-free)
__device__ __align__(16) __half g_xh[MROWS * DD];        // fp16 x
__device__ __align__(16) __half g_wt[4][DD * NHEAD];     // fp16 W^T (q,k,v,o)
__device__ __align__(16) __half g_qh[MROWS * NHEAD];     // fp16 q
__device__ __align__(16) __half g_kh[MROWS * NHEAD];     // fp16 k
__device__ __align__(16) float  g_v [MROWS * NHEAD];     // fp32 v
__device__ __align__(16) __half g_ctxh[MROWS * NHEAD];   // fp16 ctx

// ============================================================================
// Helpers
// ============================================================================
__device__ __forceinline__ uint32_t smem_u32(const void* p) {
    uint32_t a;
    asm("{ .reg .u64 t; cvta.to.shared.u64 t, %1; cvt.u32.u64 %0, t; }"
        : "=r"(a) : "l"(p));
    return a;
}

// pack two fp32 -> fp16x2 {lo, hi}, round-to-nearest
__device__ __forceinline__ uint32_t pack_f16x2(float lo, float hi) {
    uint32_t r;
    asm("cvt.rn.f16x2.f32 %0, %1, %2;" : "=r"(r) : "f"(hi), "f"(lo));
    return r;
}

// m16n8k16 fp16 MMA (fp32 accumulate)
__device__ __forceinline__ void mma_f16(float* c, const uint32_t* a, const uint32_t* b) {
    asm volatile(
        "mma.sync.aligned.m16n8k16.row.col.f32.f16.f16.f32 "
        "{%0,%1,%2,%3}, {%4,%5,%6,%7}, {%8,%9}, {%0,%1,%2,%3};"
        : "+f"(c[0]), "+f"(c[1]), "+f"(c[2]), "+f"(c[3])
        : "r"(a[0]), "r"(a[1]), "r"(a[2]), "r"(a[3]), "r"(b[0]), "r"(b[1]));
}

#define CP16(dst, src) \
    asm volatile("cp.async.cg.shared.global [%0], [%1], 16;" \
        :: "r"(dst), "l"(src) : "memory")
#define CP_COMMIT() asm volatile("cp.async.commit_group;" ::: "memory")
#define CP_WAIT2()  asm volatile("cp.async.wait_group 2;" ::: "memory")
#define CP_WAIT0()  asm volatile("cp.async.wait_group 0;" ::: "memory")

// ============================================================================
// Prepass: fp32 -> fp16 conversions
// ============================================================================
__global__ void __launch_bounds__(256)
cvt_f16(const float* __restrict__ in, __half* __restrict__ out)
{
    int i = blockIdx.x * blockDim.x + threadIdx.x;   // over groups of 4
    float4 v = ((const float4*)in)[i];
    uint2 o;
    o.x = pack_f16x2(v.x, v.y);
    o.y = pack_f16x2(v.z, v.w);
    ((uint2*)out)[i] = o;
}

// W [1024 x 1024] fp32 row-major -> Wt [1024 x 1024] fp16 (Wt[n][k] = W[k][n])
__global__ void __launch_bounds__(256)
transpose_f16(const float* __restrict__ W, __half* __restrict__ Wt)
{
    __shared__ float t[32][33];
    int bx = blockIdx.x * 32, by = blockIdx.y * 32;
    int x = bx + threadIdx.x;
    #pragma unroll
    for (int i = 0; i < 32; i += 8)
        t[threadIdx.y + i][threadIdx.x] = W[(size_t)(by + threadIdx.y + i) * 1024 + x];
    __syncthreads();
    int xo = by + threadIdx.x;
    #pragma unroll
    for (int i = 0; i < 32; i += 8)
        Wt[(size_t)(bx + threadIdx.y + i) * 1024 + xo] =
            __float2half(t[threadIdx.x][threadIdx.y + i]);
}

// ============================================================================
// FP16 tensor-core GEMM:
//   C[8192 x 1024] = (A @ Wt^T + bias) * scale
// A [M][K] fp16 row-major, Wt [N][K] fp16 row-major (both k-major).
// CTA 128x128, BK=32, 8 warps (2Mx4N), warp tile 64x32, m16n8k16.
// 4-stage cp.async. Output fp16 (outHalf=1) or fp32.
// ============================================================================
#define GBM 128
#define GBN 128
#define GBK 32
#define G_STR 20   /* b32 words per smem row (32 halves + pad 8) */
#define G_AWORDS (GBM * G_STR)                  /* 2560 u32 */
#define G_STAGE_BYTES (2 * G_AWORDS * 4)        /* A+B: 20480 */
#define G_NSTG 4
#define GSMEM (G_NSTG * G_STAGE_BYTES)          /* 81920 */

__global__ void __launch_bounds__(256, 2)
gemm_f16(const __half* __restrict__ A, const __half* __restrict__ Wt,
         const float* __restrict__ bias,
         float* __restrict__ Cf, __half* __restrict__ Ch,
         float scale, int outHalf)
{
    extern __shared__ char smraw[];
    const uint32_t smb = smem_u32(smraw);

    const int tid  = threadIdx.x;
    const int lane = tid & 31;
    const int wid  = tid >> 5;
    const int wm   = wid & 1;
    const int wn   = wid >> 1;
    const int gid  = lane >> 2;
    const int tig  = lane & 3;
    const int m0   = blockIdx.y * GBM;
    const int n0   = blockIdx.x * GBN;

    float acc[4][4][4];
    #pragma unroll
    for (int i = 0; i < 4; ++i)
        #pragma unroll
        for (int j = 0; j < 4; ++j)
            #pragma unroll
            for (int r = 0; r < 4; ++r) acc[i][j][r] = 0.f;

    const __half* Ag = A  + (size_t)m0 * 1024;
    const __half* Wg = Wt + (size_t)n0 * 1024;

    // Stage loader: A tile 128x32 fp16 + B tile 128x32 fp16, 4 chunks/thread
    auto load_stage = [&](int s, int kt) {
        const uint32_t as = smb + (uint32_t)s * G_STAGE_BYTES;
        const uint32_t bs = as + G_AWORDS * 4;
        #pragma unroll
        for (int i = 0; i < 2; ++i) {
            int idx = tid + i * 256;
            int r = idx >> 2, c = (idx & 3) << 3;   // c in halves
            CP16(as + (uint32_t)(r * G_STR * 4 + c * 2),
                 Ag + (size_t)r * 1024 + kt * GBK + c);
            CP16(bs + (uint32_t)(r * G_STR * 4 + c * 2),
                 Wg + (size_t)r * 1024 + kt * GBK + c);
        }
    };

    #pragma unroll
    for (int s = 0; s < 3; ++s) { load_stage(s, s); CP_COMMIT(); }

    for (int kt = 0; kt < 32; ++kt) {
        CP_WAIT2();
        __syncthreads();

        if (kt + 3 < 32) load_stage((kt + 3) & 3, kt + 3);
        CP_COMMIT();

        const uint32_t* a32 = (const uint32_t*)(smraw + (kt & 3) * G_STAGE_BYTES);
        const uint32_t* b32 = a32 + G_AWORDS;

        #pragma unroll
        for (int k16 = 0; k16 < 2; ++k16) {
            uint32_t a[4][4], b[4][2];
            #pragma unroll
            for (int i = 0; i < 4; ++i) {
                const uint32_t* ap = a32 + (wm * 64 + i * 16 + gid) * G_STR
                                         + k16 * 8 + tig;
                a[i][0] = ap[0];
                a[i][1] = ap[8 * G_STR];
                a[i][2] = ap[4];
                a[i][3] = ap[8 * G_STR + 4];
            }
            #pragma unroll
            for (int j = 0; j < 4; ++j) {
                const uint32_t* bp = b32 + (wn * 32 + j * 8 + gid) * G_STR
                                         + k16 * 8 + tig;
                b[j][0] = bp[0];
                b[j][1] = bp[4];
            }
            #pragma unroll
            for (int i = 0; i < 4; ++i)
                #pragma unroll
                for (int j = 0; j < 4; ++j)
                    mma_f16(acc[i][j], a[i], b[j]);
        }
    }
    CP_WAIT0();

    // Epilogue: bias + scale; fp16 or fp32 output
    #pragma unroll
    for (int i = 0; i < 4; ++i) {
        const int row = m0 + wm * 64 + i * 16 + gid;
        #pragma unroll
        for (int j = 0; j < 4; ++j) {
            const int col = n0 + wn * 32 + j * 8 + (tig << 1);
            const float b0 = bias[col], b1 = bias[col + 1];
            float v00 = (acc[i][j][0] + b0) * scale;
            float v01 = (acc[i][j][1] + b1) * scale;
            float v10 = (acc[i][j][2] + b0) * scale;
            float v11 = (acc[i][j][3] + b1) * scale;
            if (outHalf) {
                *(uint32_t*)(Ch + (size_t)row * 1024 + col)       = pack_f16x2(v00, v01);
                *(uint32_t*)(Ch + (size_t)(row + 8) * 1024 + col) = pack_f16x2(v10, v11);
            } else {
                *(float2*)(Cf + (size_t)row * 1024 + col)       = make_float2(v00, v01);
                *(float2*)(Cf + (size_t)(row + 8) * 1024 + col) = make_float2(v10, v11);
            }
        }
    }
}

// ============================================================================
// FP16 tensor-core flash attention with cp.async pipeline.
// CTA: 128 q-rows of one (b,h); 8 warps x 16 q-rows; 64-key tiles, 32 iters.
// QK^T: fp16 mma (Q,K fp16 from GEMM). PV: fp16 mma, P register passthrough,
// V (fp32 gmem) transposed to fp16 pairs in smem.
// K fp16 double-buffered; V fp32 single-buffer staging.
// ============================================================================
#define FQ 128
#define QK_STR 36   /* b32 words per Q/K smem row (64 halves = 32 words + pad 4) */
#define VS_STR 68
#define VT_STR 36
// bytes: Qs 128*36*4 + Ks 2*64*36*4 + Vs 64*68*4 + Vt 64*36*4
#define FL_SMEM (128*QK_STR*4 + 2*64*QK_STR*4 + 64*VS_STR*4 + 64*VT_STR*4) /* 63488 */

__global__ void __launch_bounds__(256, 2)
flash_tc(const __half* __restrict__ Q, const __half* __restrict__ K,
         const float* __restrict__ V, __half* __restrict__ O)
{
    extern __shared__ char smraw[];
    uint32_t* Qs32 = (uint32_t*)smraw;                    // [128][36]
    uint32_t* Ks32 = Qs32 + 128 * QK_STR;                 // [2][64][36]
    float*    Vs   = (float*)(Ks32 + 2 * 64 * QK_STR);    // [64][68]
    uint32_t* Vt   = (uint32_t*)(Vs + 64 * VS_STR);       // [64][36]

    const uint32_t smb    = smem_u32(smraw);
    const uint32_t ks_smb = smb + 128 * QK_STR * 4;
    const uint32_t vs_smb = ks_smb + 2 * 64 * QK_STR * 4;

    const int tid  = threadIdx.x;
    const int w    = tid >> 5;
    const int lane = tid & 31;
    const int gid  = lane >> 2;
    const int tig  = lane & 3;
    const int bh   = blockIdx.y;
    const int b    = bh >> 4;
    const int h    = bh & 15;
    const int q0   = blockIdx.x * FQ;

    const __half* Qg = Q + ((size_t)b * SS + q0) * NHEAD + h * HDIM;
    const __half* Kg = K + (size_t)b * SS * NHEAD + h * HDIM;
    const float*  Vg = V + (size_t)b * SS * NHEAD + h * HDIM;

    // K tile 64x64 fp16 = 8KB = 512 chunks = 2/thread
    auto load_k = [&](uint32_t dstbase, const __half* src) {
        #pragma unroll
        for (int i = 0; i < 2; ++i) {
            int idx = tid + i * 256;
            int r = idx >> 3, c = (idx & 7) << 3;   // c in halves
            CP16(dstbase + (uint32_t)(r * QK_STR * 4 + c * 2),
                 src + (size_t)r * NHEAD + c);
        }
    };
    // V tile 64x64 fp32 = 16KB = 1024 chunks = 4/thread
    auto load_v = [&](const float* src) {
        #pragma unroll
        for (int i = 0; i < 4; ++i) {
            int idx = tid + i * 256;
            int r = idx >> 4, c = (idx & 15) << 2;
            CP16(vs_smb + (uint32_t)(r * VS_STR + c) * 4,
                 src + (size_t)r * NHEAD + c);
        }
    };

    // Prologue: K(0) -> buf 0, V(0) -> staging
    load_k(ks_smb, Kg);
    load_v(Vg);
    CP_COMMIT();

    // Load Q tile (128 x 64 fp16) while DMA flies: 16B = 8 halves per chunk
    #pragma unroll
    for (int i = 0; i < 4; ++i) {
        int idx = tid + i * 256;
        int r = idx >> 3, c8 = idx & 7;
        uint4 t = *(const uint4*)(Qg + (size_t)r * NHEAD + c8 * 8);
        *(uint4*)(Qs32 + r * QK_STR + c8 * 4) = t;
    }

    float m_[2] = {-1e30f, -1e30f};
    float l_[2] = {0.f, 0.f};
    float o[8][4];
    #pragma unroll
    for (int nt = 0; nt < 8; ++nt)
        #pragma unroll
        for (int r = 0; r < 4; ++r) o[nt][r] = 0.f;

    const int qr = w * 16 + gid;
    const uint32_t* qrow0 = Qs32 + qr * QK_STR;
    const int jp = 4 * w + tig;                  // V-transpose pair column

    for (int it = 0; it < 32; ++it) {
        const int t0 = it * 64;
        CP_WAIT0();
        __syncthreads();

        // Transpose V -> Vt fp16 pairs: Vt[d][jp] = {V[2jp][d], V[2jp+1][d]}
        #pragma unroll
        for (int itd = 0; itd < 8; ++itd) {
            int d = gid + 8 * itd;
            float lo = Vs[(2 * jp)     * VS_STR + d];
            float hi = Vs[(2 * jp + 1) * VS_STR + d];
            Vt[d * VT_STR + jp] = pack_f16x2(lo, hi);
        }
        __syncthreads();     // Vt visible; Vs free for next V

        if (it + 1 < 32) {
            load_k(ks_smb + (uint32_t)(((it + 1) & 1) * 64 * QK_STR) * 4,
                   Kg + (size_t)(t0 + 64) * NHEAD);
            load_v(Vg + (size_t)(t0 + 64) * NHEAD);
        }
        CP_COMMIT();

        const uint32_t* Ksb = Ks32 + (it & 1) * 64 * QK_STR;

        // S = Q K^T (fp16 mma, k16 x 4), warp tile 16 x 64
        float s[8][4];
        #pragma unroll
        for (int nt = 0; nt < 8; ++nt)
            #pragma unroll
            for (int r = 0; r < 4; ++r) s[nt][r] = 0.f;

        #pragma unroll
        for (int ks = 0; ks < 4; ++ks) {
            uint32_t a[4];
            const uint32_t* qp = qrow0 + ks * 8 + tig;
            a[0] = qp[0];
            a[1] = qp[8 * QK_STR];
            a[2] = qp[4];
            a[3] = qp[8 * QK_STR + 4];
            #pragma unroll
            for (int nt = 0; nt < 8; ++nt) {
                const uint32_t* kp = Ksb + (nt * 8 + gid) * QK_STR + ks * 8 + tig;
                uint32_t bb[2];
                bb[0] = kp[0];
                bb[1] = kp[4];
                mma_f16(s[nt], a, bb);
            }
        }

        // Online softmax per row-half
        #pragma unroll
        for (int hh = 0; hh < 2; ++hh) {
            const int c0 = 2 * hh, c1 = c0 + 1;
            float mt = fmaxf(s[0][c0], s[0][c1]);
            #pragma unroll
            for (int nt = 1; nt < 8; ++nt)
                mt = fmaxf(mt, fmaxf(s[nt][c0], s[nt][c1]));
            mt = fmaxf(mt, __shfl_xor_sync(0xffffffffu, mt, 1));
            mt = fmaxf(mt, __shfl_xor_sync(0xffffffffu, mt, 2));
            float mnew = fmaxf(m_[hh], mt);
            float corr = __expf(m_[hh] - mnew);
            m_[hh] = mnew;
            float ls = 0.f;
            #pragma unroll
            for (int nt = 0; nt < 8; ++nt) {
                s[nt][c0] = __expf(s[nt][c0] - mnew);
                s[nt][c1] = __expf(s[nt][c1] - mnew);
                ls += s[nt][c0] + s[nt][c1];
            }
            ls += __shfl_xor_sync(0xffffffffu, ls, 1);
            ls += __shfl_xor_sync(0xffffffffu, ls, 2);
            l_[hh] = l_[hh] * corr + ls;
            #pragma unroll
            for (int nt = 0; nt < 8; ++nt) {
                o[nt][c0] *= corr;
                o[nt][c1] *= corr;
            }
        }

        // Pack P: S C-frag -> fp16 A-frag (registers only)
        uint32_t pa[4][4];
        #pragma unroll
        for (int kc = 0; kc < 4; ++kc) {
            pa[kc][0] = pack_f16x2(s[2 * kc][0],     s[2 * kc][1]);
            pa[kc][1] = pack_f16x2(s[2 * kc][2],     s[2 * kc][3]);
            pa[kc][2] = pack_f16x2(s[2 * kc + 1][0], s[2 * kc + 1][1]);
            pa[kc][3] = pack_f16x2(s[2 * kc + 1][2], s[2 * kc + 1][3]);
        }

        // O += P V (fp16 mma), warp tile 16 x 64
        #pragma unroll
        for (int kc = 0; kc < 4; ++kc) {
            #pragma unroll
            for (int nt = 0; nt < 8; ++nt) {
                const uint32_t* vp = Vt + (nt * 8 + gid) * VT_STR + kc * 8 + tig;
                uint32_t bb[2];
                bb[0] = vp[0];
                bb[1] = vp[4];
                mma_f16(o[nt], pa[kc], bb);
            }
        }
    }

    // Epilogue: normalize, store ctx as fp16
    const float inv0 = 1.f / l_[0];
    const float inv1 = 1.f / l_[1];
    __half* Og = O + ((size_t)b * SS + q0 + qr) * NHEAD + h * HDIM;
    #pragma unroll
    for (int nt = 0; nt < 8; ++nt) {
        *(uint32_t*)(Og + nt * 8 + 2 * tig) =
            pack_f16x2(o[nt][0] * inv0, o[nt][1] * inv0);
        *(uint32_t*)(Og + (size_t)8 * NHEAD + nt * 8 + 2 * tig) =
            pack_f16x2(o[nt][2] * inv1, o[nt][3] * inv1);
    }
}

// ============================================================================
extern "C" void kernel_launch(void* const* d_in, const int* in_sizes, int n_in,
                              void* d_out, int out_size)
{
    (void)in_sizes; (void)n_in; (void)out_size;
    const float* x  = (const float*)d_in[0];
    const float* Wq = (const float*)d_in[1];
    const float* bq = (const float*)d_in[2];
    const float* Wk = (const float*)d_in[3];
    const float* bk = (const float*)d_in[4];
    const float* Wv = (const float*)d_in[5];
    const float* bv = (const float*)d_in[6];
    const float* Wo = (const float*)d_in[7];
    const float* bo = (const float*)d_in[8];
    float* out = (float*)d_out;

    __half *xh, *wt, *qh, *kh, *ctxh;
    float  *vp;
    cudaGetSymbolAddress((void**)&xh,   g_xh);
    cudaGetSymbolAddress((void**)&wt,   g_wt);
    cudaGetSymbolAddress((void**)&qh,   g_qh);
    cudaGetSymbolAddress((void**)&kh,   g_kh);
    cudaGetSymbolAddress((void**)&vp,   g_v);
    cudaGetSymbolAddress((void**)&ctxh, g_ctxh);
    __half* wqt = wt;
    __half* wkt = wt + (size_t)DD * NHEAD;
    __half* wvt = wt + 2 * (size_t)DD * NHEAD;
    __half* wot = wt + 3 * (size_t)DD * NHEAD;

    cudaFuncSetAttribute(gemm_f16,
                         cudaFuncAttributeMaxDynamicSharedMemorySize, GSMEM);
    cudaFuncSetAttribute(flash_tc,
                         cudaFuncAttributeMaxDynamicSharedMemorySize, FL_SMEM);

    // Prepass: x -> fp16 flat; W -> fp16 transposed
    cvt_f16<<<(MROWS * DD / 4) / 256, 256>>>(x, xh);
    dim3 tgrid(32, 32), tblk(32, 8);
    transpose_f16<<<tgrid, tblk>>>(Wq, wqt);
    transpose_f16<<<tgrid, tblk>>>(Wk, wkt);
    transpose_f16<<<tgrid, tblk>>>(Wv, wvt);
    transpose_f16<<<tgrid, tblk>>>(Wo, wot);

    dim3 ggrid(NHEAD / GBN, MROWS / GBM);  // (8, 64)

    // QKV projections (1/sqrt(HD) folded into Q); q,k out fp16, v out fp32
    gemm_f16<<<ggrid, 256, GSMEM>>>(xh, wqt, bq, nullptr, qh, 0.125f, 1);
    gemm_f16<<<ggrid, 256, GSMEM>>>(xh, wkt, bk, nullptr, kh, 1.0f, 1);
    gemm_f16<<<ggrid, 256, GSMEM>>>(xh, wvt, bv, vp, nullptr, 1.0f, 0);

    // FP16 tensor-core flash attention; ctx out fp16
    flash_tc<<<dim3(SS / FQ, BB * HH), 256, FL_SMEM>>>(qh, kh, vp, ctxh);

    // Output projection (fp32 out)
    gemm_f16<<<ggrid, 256, GSMEM>>>(ctxh, wot, bo, out, nullptr, 1.0f, 0);
}

// round 8
// speedup vs baseline: 6.3235x; 1.0795x over previous
#include <cuda_runtime.h>
#include <cuda_fp16.h>
#include <cstdint>
#include <math.h>

// ============================================================================
// Problem constants
// ============================================================================
#define BB 4
#define SS 2048
#define DD 1024
#define HH 16
#define HDIM 64
#define MROWS (BB * SS)     /* 8192 */
#define NHEAD (HH * HDIM)   /* 1024 */

// Scratch (device globals: allocation-free)
__device__ __align__(16) __half g_xh[MROWS * DD];        // fp16 x
__device__ __align__(16) __half g_wt[4][DD * NHEAD];     // fp16 W^T (q,k,v,o)
__device__ __align__(16) __half g_qh[MROWS * NHEAD];     // fp16 q
__device__ __align__(16) __half g_kh[MROWS * NHEAD];     // fp16 k
__device__ __align__(16) float  g_v [MROWS * NHEAD];     // fp32 v
__device__ __align__(16) __half g_ctxh[MROWS * NHEAD];   // fp16 ctx

// ============================================================================
// Helpers
// ============================================================================
__device__ __forceinline__ uint32_t smem_u32(const void* p) {
    uint32_t a;
    asm("{ .reg .u64 t; cvta.to.shared.u64 t, %1; cvt.u32.u64 %0, t; }"
        : "=r"(a) : "l"(p));
    return a;
}

// pack two fp32 -> fp16x2 {lo, hi}, round-to-nearest
__device__ __forceinline__ uint32_t pack_f16x2(float lo, float hi) {
    uint32_t r;
    asm("cvt.rn.f16x2.f32 %0, %1, %2;" : "=r"(r) : "f"(hi), "f"(lo));
    return r;
}

// m16n8k16 fp16 MMA (fp32 accumulate)
__device__ __forceinline__ void mma_f16(float* c, const uint32_t* a, const uint32_t* b) {
    asm volatile(
        "mma.sync.aligned.m16n8k16.row.col.f32.f16.f16.f32 "
        "{%0,%1,%2,%3}, {%4,%5,%6,%7}, {%8,%9}, {%0,%1,%2,%3};"
        : "+f"(c[0]), "+f"(c[1]), "+f"(c[2]), "+f"(c[3])
        : "r"(a[0]), "r"(a[1]), "r"(a[2]), "r"(a[3]), "r"(b[0]), "r"(b[1]));
}

// ldmatrix x4: four 8x8 b16 matrices, per-lane row addresses
__device__ __forceinline__ void ldm_x4(uint32_t* r, uint32_t addr) {
    asm volatile(
        "ldmatrix.sync.aligned.m8n8.x4.shared.b16 {%0,%1,%2,%3}, [%4];"
        : "=r"(r[0]), "=r"(r[1]), "=r"(r[2]), "=r"(r[3]) : "r"(addr));
}

#define CP16(dst, src) \
    asm volatile("cp.async.cg.shared.global [%0], [%1], 16;" \
        :: "r"(dst), "l"(src) : "memory")
#define CP_COMMIT() asm volatile("cp.async.commit_group;" ::: "memory")
#define CP_WAIT2()  asm volatile("cp.async.wait_group 2;" ::: "memory")
#define CP_WAIT0()  asm volatile("cp.async.wait_group 0;" ::: "memory")

// ============================================================================
// Prepass: fp32 -> fp16 conversions
// ============================================================================
__global__ void __launch_bounds__(256)
cvt_f16(const float* __restrict__ in, __half* __restrict__ out)
{
    int i = blockIdx.x * blockDim.x + threadIdx.x;
    float4 v = ((const float4*)in)[i];
    uint2 o;
    o.x = pack_f16x2(v.x, v.y);
    o.y = pack_f16x2(v.z, v.w);
    ((uint2*)out)[i] = o;
}

__global__ void __launch_bounds__(256)
transpose_f16(const float* __restrict__ W, __half* __restrict__ Wt)
{
    __shared__ float t[32][33];
    int bx = blockIdx.x * 32, by = blockIdx.y * 32;
    int x = bx + threadIdx.x;
    #pragma unroll
    for (int i = 0; i < 32; i += 8)
        t[threadIdx.y + i][threadIdx.x] = W[(size_t)(by + threadIdx.y + i) * 1024 + x];
    __syncthreads();
    int xo = by + threadIdx.x;
    #pragma unroll
    for (int i = 0; i < 32; i += 8)
        Wt[(size_t)(bx + threadIdx.y + i) * 1024 + xo] =
            __float2half(t[threadIdx.x][threadIdx.y + i]);
}

// ============================================================================
// FP16 GEMM core (device body shared by QKV-merged and single kernels)
// CTA 128x128, BK=32, 8 warps (2Mx4N), warp tile 64x32, m16n8k16.
// ============================================================================
#define GBM 128
#define GBN 128
#define GBK 32
#define G_STR 20
#define G_AWORDS (GBM * G_STR)
#define G_STAGE_BYTES (2 * G_AWORDS * 4)
#define G_NSTG 4
#define GSMEM (G_NSTG * G_STAGE_BYTES)

__device__ __forceinline__ void
gemm_body(char* smraw, const __half* __restrict__ A, const __half* __restrict__ Wt,
          const float* __restrict__ bias,
          float* __restrict__ Cf, __half* __restrict__ Ch,
          float scale, int outHalf, int bx, int by)
{
    const uint32_t smb = smem_u32(smraw);

    const int tid  = threadIdx.x;
    const int lane = tid & 31;
    const int wid  = tid >> 5;
    const int wm   = wid & 1;
    const int wn   = wid >> 1;
    const int gid  = lane >> 2;
    const int tig  = lane & 3;
    const int m0   = by * GBM;
    const int n0   = bx * GBN;

    float acc[4][4][4];
    #pragma unroll
    for (int i = 0; i < 4; ++i)
        #pragma unroll
        for (int j = 0; j < 4; ++j)
            #pragma unroll
            for (int r = 0; r < 4; ++r) acc[i][j][r] = 0.f;

    const __half* Ag = A  + (size_t)m0 * 1024;
    const __half* Wg = Wt + (size_t)n0 * 1024;

    auto load_stage = [&](int s, int kt) {
        const uint32_t as = smb + (uint32_t)s * G_STAGE_BYTES;
        const uint32_t bs = as + G_AWORDS * 4;
        #pragma unroll
        for (int i = 0; i < 2; ++i) {
            int idx = tid + i * 256;
            int r = idx >> 2, c = (idx & 3) << 3;
            CP16(as + (uint32_t)(r * G_STR * 4 + c * 2),
                 Ag + (size_t)r * 1024 + kt * GBK + c);
            CP16(bs + (uint32_t)(r * G_STR * 4 + c * 2),
                 Wg + (size_t)r * 1024 + kt * GBK + c);
        }
    };

    #pragma unroll
    for (int s = 0; s < 3; ++s) { load_stage(s, s); CP_COMMIT(); }

    for (int kt = 0; kt < 32; ++kt) {
        CP_WAIT2();
        __syncthreads();

        if (kt + 3 < 32) load_stage((kt + 3) & 3, kt + 3);
        CP_COMMIT();

        const uint32_t* a32 = (const uint32_t*)(smraw + (kt & 3) * G_STAGE_BYTES);
        const uint32_t* b32 = a32 + G_AWORDS;

        #pragma unroll
        for (int k16 = 0; k16 < 2; ++k16) {
            uint32_t a[4][4], b[4][2];
            #pragma unroll
            for (int i = 0; i < 4; ++i) {
                const uint32_t* ap = a32 + (wm * 64 + i * 16 + gid) * G_STR
                                         + k16 * 8 + tig;
                a[i][0] = ap[0];
                a[i][1] = ap[8 * G_STR];
                a[i][2] = ap[4];
                a[i][3] = ap[8 * G_STR + 4];
            }
            #pragma unroll
            for (int j = 0; j < 4; ++j) {
                const uint32_t* bp = b32 + (wn * 32 + j * 8 + gid) * G_STR
                                         + k16 * 8 + tig;
                b[j][0] = bp[0];
                b[j][1] = bp[4];
            }
            #pragma unroll
            for (int i = 0; i < 4; ++i)
                #pragma unroll
                for (int j = 0; j < 4; ++j)
                    mma_f16(acc[i][j], a[i], b[j]);
        }
    }
    CP_WAIT0();

    #pragma unroll
    for (int i = 0; i < 4; ++i) {
        const int row = m0 + wm * 64 + i * 16 + gid;
        #pragma unroll
        for (int j = 0; j < 4; ++j) {
            const int col = n0 + wn * 32 + j * 8 + (tig << 1);
            const float b0 = bias[col], b1 = bias[col + 1];
            float v00 = (acc[i][j][0] + b0) * scale;
            float v01 = (acc[i][j][1] + b1) * scale;
            float v10 = (acc[i][j][2] + b0) * scale;
            float v11 = (acc[i][j][3] + b1) * scale;
            if (outHalf) {
                *(uint32_t*)(Ch + (size_t)row * 1024 + col)       = pack_f16x2(v00, v01);
                *(uint32_t*)(Ch + (size_t)(row + 8) * 1024 + col) = pack_f16x2(v10, v11);
            } else {
                *(float2*)(Cf + (size_t)row * 1024 + col)       = make_float2(v00, v01);
                *(float2*)(Cf + (size_t)(row + 8) * 1024 + col) = make_float2(v10, v11);
            }
        }
    }
}

// Merged QKV: blockIdx.z selects {q, k, v}
__global__ void __launch_bounds__(256, 2)
gemm_qkv(const __half* __restrict__ xh,
         const __half* __restrict__ wq, const __half* __restrict__ wk,
         const __half* __restrict__ wv,
         const float* __restrict__ bq, const float* __restrict__ bk,
         const float* __restrict__ bv,
         __half* __restrict__ qh, __half* __restrict__ kh,
         float* __restrict__ vf)
{
    extern __shared__ char smraw[];
    const int z = blockIdx.z;
    const __half* Wt  = (z == 0) ? wq : (z == 1) ? wk : wv;
    const float*  bia = (z == 0) ? bq : (z == 1) ? bk : bv;
    if (z == 2)
        gemm_body(smraw, xh, Wt, bia, vf, nullptr, 1.0f, 0,
                  blockIdx.x, blockIdx.y);
    else
        gemm_body(smraw, xh, Wt, bia, nullptr, (z == 0) ? qh : kh,
                  (z == 0) ? 0.125f : 1.0f, 1, blockIdx.x, blockIdx.y);
}

// Single GEMM (output projection, fp32 out)
__global__ void __launch_bounds__(256, 2)
gemm_f16(const __half* __restrict__ A, const __half* __restrict__ Wt,
         const float* __restrict__ bias, float* __restrict__ Cf, float scale)
{
    extern __shared__ char smraw[];
    gemm_body(smraw, A, Wt, bias, Cf, nullptr, scale, 0,
              blockIdx.x, blockIdx.y);
}

// ============================================================================
// FP16 flash attention, ldmatrix fragment loads, cp.async pipeline.
// ============================================================================
#define FQ 128
#define QK_STR 36
#define VS_STR 68
#define VT_STR 36
#define FL_SMEM (128*QK_STR*4 + 2*64*QK_STR*4 + 64*VS_STR*4 + 64*VT_STR*4)

__global__ void __launch_bounds__(256, 2)
flash_tc(const __half* __restrict__ Q, const __half* __restrict__ K,
         const float* __restrict__ V, __half* __restrict__ O)
{
    extern __shared__ char smraw[];
    uint32_t* Qs32 = (uint32_t*)smraw;                    // [128][36]
    uint32_t* Ks32 = Qs32 + 128 * QK_STR;                 // [2][64][36]
    float*    Vs   = (float*)(Ks32 + 2 * 64 * QK_STR);    // [64][68]
    uint32_t* Vt   = (uint32_t*)(Vs + 64 * VS_STR);       // [64][36]

    const uint32_t smb    = smem_u32(smraw);
    const uint32_t ks_smb = smb + 128 * QK_STR * 4;
    const uint32_t vs_smb = ks_smb + 2 * 64 * QK_STR * 4;
    const uint32_t vt_smb = vs_smb + 64 * VS_STR * 4;

    const int tid  = threadIdx.x;
    const int w    = tid >> 5;
    const int lane = tid & 31;
    const int gid  = lane >> 2;
    const int tig  = lane & 3;
    const int bh   = blockIdx.y;
    const int b    = bh >> 4;
    const int h    = bh & 15;
    const int q0   = blockIdx.x * FQ;

    const __half* Qg = Q + ((size_t)b * SS + q0) * NHEAD + h * HDIM;
    const __half* Kg = K + (size_t)b * SS * NHEAD + h * HDIM;
    const float*  Vg = V + (size_t)b * SS * NHEAD + h * HDIM;

    auto load_k = [&](uint32_t dstbase, const __half* src) {
        #pragma unroll
        for (int i = 0; i < 2; ++i) {
            int idx = tid + i * 256;
            int r = idx >> 3, c = (idx & 7) << 3;
            CP16(dstbase + (uint32_t)(r * QK_STR * 4 + c * 2),
                 src + (size_t)r * NHEAD + c);
        }
    };
    auto load_v = [&](const float* src) {
        #pragma unroll
        for (int i = 0; i < 4; ++i) {
            int idx = tid + i * 256;
            int r = idx >> 4, c = (idx & 15) << 2;
            CP16(vs_smb + (uint32_t)(r * VS_STR + c) * 4,
                 src + (size_t)r * NHEAD + c);
        }
    };

    load_k(ks_smb, Kg);
    load_v(Vg);
    CP_COMMIT();

    // Load Q tile (128 x 64 fp16)
    #pragma unroll
    for (int i = 0; i < 4; ++i) {
        int idx = tid + i * 256;
        int r = idx >> 3, c8 = idx & 7;
        uint4 t = *(const uint4*)(Qg + (size_t)r * NHEAD + c8 * 8);
        *(uint4*)(Qs32 + r * QK_STR + c8 * 4) = t;
    }

    float m_[2] = {-1e30f, -1e30f};
    float l_[2] = {0.f, 0.f};
    float o[8][4];
    #pragma unroll
    for (int nt = 0; nt < 8; ++nt)
        #pragma unroll
        for (int r = 0; r < 4; ++r) o[nt][r] = 0.f;

    const int qr = w * 16 + gid;
    const int jp = 4 * w + tig;

    // ldmatrix per-lane address bases
    // A-frag (Q): m0 rows w*16+(l&7), m1 +8 rows, m2 +16B, m3 +8rows+16B
    const int arow = w * 16 + (lane & 7) + (((lane >> 3) & 1) << 3);
    const uint32_t q_lm = smb + (uint32_t)(arow * QK_STR) * 4
                              + (((lane >> 4) & 1) << 4);
    // B-frag (K/Vt): m0 rows p*16+(l&7) @+0, m1 same rows @+16B,
    //                m2 rows +8 @+0, m3 rows +8 @+16B
    const int brow = (lane & 7) + (((lane >> 4) & 1) << 3);
    const uint32_t bcol = (((lane >> 3) & 1) << 4);
    const uint32_t k_lm0 = ks_smb + (uint32_t)(brow * QK_STR) * 4 + bcol;
    const uint32_t v_lm  = vt_smb + (uint32_t)(brow * VT_STR) * 4 + bcol;

    for (int it = 0; it < 32; ++it) {
        const int t0 = it * 64;
        CP_WAIT0();
        __syncthreads();

        // Transpose V -> Vt fp16 pairs
        #pragma unroll
        for (int itd = 0; itd < 8; ++itd) {
            int d = gid + 8 * itd;
            float lo = Vs[(2 * jp)     * VS_STR + d];
            float hi = Vs[(2 * jp + 1) * VS_STR + d];
            Vt[d * VT_STR + jp] = pack_f16x2(lo, hi);
        }
        __syncthreads();

        if (it + 1 < 32) {
            load_k(ks_smb + (uint32_t)(((it + 1) & 1) * 64 * QK_STR) * 4,
                   Kg + (size_t)(t0 + 64) * NHEAD);
            load_v(Vg + (size_t)(t0 + 64) * NHEAD);
        }
        CP_COMMIT();

        const uint32_t klm = k_lm0 + (uint32_t)((it & 1) * 64 * QK_STR) * 4;

        // S = Q K^T (fp16 mma, ldmatrix frags)
        float s[8][4];
        #pragma unroll
        for (int nt = 0; nt < 8; ++nt)
            #pragma unroll
            for (int r = 0; r < 4; ++r) s[nt][r] = 0.f;

        #pragma unroll
        for (int ks = 0; ks < 4; ++ks) {
            uint32_t a[4];
            ldm_x4(a, q_lm + ks * 32);
            #pragma unroll
            for (int p = 0; p < 4; ++p) {
                uint32_t kb[4];
                ldm_x4(kb, klm + (uint32_t)(p * 16 * QK_STR) * 4 + ks * 32);
                mma_f16(s[2 * p],     a, kb);
                mma_f16(s[2 * p + 1], a, kb + 2);
            }
        }

        // Online softmax per row-half
        #pragma unroll
        for (int hh = 0; hh < 2; ++hh) {
            const int c0 = 2 * hh, c1 = c0 + 1;
            float mt = fmaxf(s[0][c0], s[0][c1]);
            #pragma unroll
            for (int nt = 1; nt < 8; ++nt)
                mt = fmaxf(mt, fmaxf(s[nt][c0], s[nt][c1]));
            mt = fmaxf(mt, __shfl_xor_sync(0xffffffffu, mt, 1));
            mt = fmaxf(mt, __shfl_xor_sync(0xffffffffu, mt, 2));
            float mnew = fmaxf(m_[hh], mt);
            float corr = __expf(m_[hh] - mnew);
            m_[hh] = mnew;
            float ls = 0.f;
            #pragma unroll
            for (int nt = 0; nt < 8; ++nt) {
                s[nt][c0] = __expf(s[nt][c0] - mnew);
                s[nt][c1] = __expf(s[nt][c1] - mnew);
                ls += s[nt][c0] + s[nt][c1];
            }
            ls += __shfl_xor_sync(0xffffffffu, ls, 1);
            ls += __shfl_xor_sync(0xffffffffu, ls, 2);
            l_[hh] = l_[hh] * corr + ls;
            #pragma unroll
            for (int nt = 0; nt < 8; ++nt) {
                o[nt][c0] *= corr;
                o[nt][c1] *= corr;
            }
        }

        // Pack P: S C-frag -> fp16 A-frag (registers only)
        uint32_t pa[4][4];
        #pragma unroll
        for (int kc = 0; kc < 4; ++kc) {
            pa[kc][0] = pack_f16x2(s[2 * kc][0],     s[2 * kc][1]);
            pa[kc][1] = pack_f16x2(s[2 * kc][2],     s[2 * kc][3]);
            pa[kc][2] = pack_f16x2(s[2 * kc + 1][0], s[2 * kc + 1][1]);
            pa[kc][3] = pack_f16x2(s[2 * kc + 1][2], s[2 * kc + 1][3]);
        }

        // O += P V (fp16 mma, ldmatrix V frags)
        #pragma unroll
        for (int kc = 0; kc < 4; ++kc) {
            #pragma unroll
            for (int p = 0; p < 4; ++p) {
                uint32_t vb[4];
                ldm_x4(vb, v_lm + (uint32_t)(p * 16 * VT_STR) * 4 + kc * 32);
                mma_f16(o[2 * p],     pa[kc], vb);
                mma_f16(o[2 * p + 1], pa[kc], vb + 2);
            }
        }
    }

    // Epilogue: normalize, store ctx as fp16
    const float inv0 = 1.f / l_[0];
    const float inv1 = 1.f / l_[1];
    __half* Og = O + ((size_t)b * SS + q0 + qr) * NHEAD + h * HDIM;
    #pragma unroll
    for (int nt = 0; nt < 8; ++nt) {
        *(uint32_t*)(Og + nt * 8 + 2 * tig) =
            pack_f16x2(o[nt][0] * inv0, o[nt][1] * inv0);
        *(uint32_t*)(Og + (size_t)8 * NHEAD + nt * 8 + 2 * tig) =
            pack_f16x2(o[nt][2] * inv1, o[nt][3] * inv1);
    }
}

// ============================================================================
extern "C" void kernel_launch(void* const* d_in, const int* in_sizes, int n_in,
                              void* d_out, int out_size)
{
    (void)in_sizes; (void)n_in; (void)out_size;
    const float* x  = (const float*)d_in[0];
    const float* Wq = (const float*)d_in[1];
    const float* bq = (const float*)d_in[2];
    const float* Wk = (const float*)d_in[3];
    const float* bk = (const float*)d_in[4];
    const float* Wv = (const float*)d_in[5];
    const float* bv = (const float*)d_in[6];
    const float* Wo = (const float*)d_in[7];
    const float* bo = (const float*)d_in[8];
    float* out = (float*)d_out;

    __half *xh, *wt, *qh, *kh, *ctxh;
    float  *vp;
    cudaGetSymbolAddress((void**)&xh,   g_xh);
    cudaGetSymbolAddress((void**)&wt,   g_wt);
    cudaGetSymbolAddress((void**)&qh,   g_qh);
    cudaGetSymbolAddress((void**)&kh,   g_kh);
    cudaGetSymbolAddress((void**)&vp,   g_v);
    cudaGetSymbolAddress((void**)&ctxh, g_ctxh);
    __half* wqt = wt;
    __half* wkt = wt + (size_t)DD * NHEAD;
    __half* wvt = wt + 2 * (size_t)DD * NHEAD;
    __half* wot = wt + 3 * (size_t)DD * NHEAD;

    cudaFuncSetAttribute(gemm_qkv,
                         cudaFuncAttributeMaxDynamicSharedMemorySize, GSMEM);
    cudaFuncSetAttribute(gemm_f16,
                         cudaFuncAttributeMaxDynamicSharedMemorySize, GSMEM);
    cudaFuncSetAttribute(flash_tc,
                         cudaFuncAttributeMaxDynamicSharedMemorySize, FL_SMEM);

    // Prepass: x -> fp16 flat; W -> fp16 transposed
    cvt_f16<<<(MROWS * DD / 4) / 256, 256>>>(x, xh);
    dim3 tgrid(32, 32), tblk(32, 8);
    transpose_f16<<<tgrid, tblk>>>(Wq, wqt);
    transpose_f16<<<tgrid, tblk>>>(Wk, wkt);
    transpose_f16<<<tgrid, tblk>>>(Wv, wvt);
    transpose_f16<<<tgrid, tblk>>>(Wo, wot);

    // Merged QKV projections (single launch, z selects target)
    dim3 qkvgrid(NHEAD / GBN, MROWS / GBM, 3);  // (8, 64, 3)
    gemm_qkv<<<qkvgrid, 256, GSMEM>>>(xh, wqt, wkt, wvt, bq, bk, bv,
                                      qh, kh, vp);

    // FP16 flash attention (ldmatrix); ctx out fp16
    flash_tc<<<dim3(SS / FQ, BB * HH), 256, FL_SMEM>>>(qh, kh, vp, ctxh);

    // Output projection (fp32 out)
    dim3 ggrid(NHEAD / GBN, MROWS / GBM);
    gemm_f16<<<ggrid, 256, GSMEM>>>(ctxh, wot, bo, out, 1.0f);
}